// round 2
// baseline (speedup 1.0000x reference)
#include <cuda_runtime.h>
#include <math.h>

// Problem constants
#define BATCH 2
#define SEQ   2048
#define CDIM  256
#define HEADS 8
#define HDIM  32
#define TOK   4096          // tokens per stream (BATCH*SEQ)
#define TTOK  8192          // total tokens (both streams)
#define HID   1024

// qk scale: 32^-0.25 (applied to both sides in reference)
#define QK_SCALE 0.42044820762685725f

// ---------------- scratch (static device allocations) ----------------
__device__ float g_n [TTOK * CDIM];        // ln1 output
__device__ float g_qk[TTOK * CDIM];        // qk projection (scaled)
__device__ float g_v [TTOK * CDIM];        // v projection
__device__ float g_m [TTOK * CDIM];        // attention output
__device__ float g_xm[TTOK * 2 * CDIM];    // concat(x, m@merge_w^T), ld=512
__device__ float g_h1[TTOK * HID];         // fc1+gelu output
__device__ float g_h2[TTOK * CDIM];        // fc2 output

// ---------------- LayerNorm (warp per token) ----------------
__global__ void ln1_kernel(const float* __restrict__ x0, const float* __restrict__ x1,
                           const float* __restrict__ w, const float* __restrict__ b,
                           float* __restrict__ out)
{
    int gwarp = (blockIdx.x * blockDim.x + threadIdx.x) >> 5;
    int lane = threadIdx.x & 31;
    if (gwarp >= TTOK) return;
    const float* x = (gwarp < TOK) ? (x0 + (size_t)gwarp * CDIM)
                                   : (x1 + (size_t)(gwarp - TOK) * CDIM);
    float4 a = ((const float4*)x)[lane];
    float4 c = ((const float4*)x)[lane + 32];
    float sum = a.x + a.y + a.z + a.w + c.x + c.y + c.z + c.w;
    float sq  = a.x*a.x + a.y*a.y + a.z*a.z + a.w*a.w
              + c.x*c.x + c.y*c.y + c.z*c.z + c.w*c.w;
    #pragma unroll
    for (int o = 16; o; o >>= 1) {
        sum += __shfl_xor_sync(0xffffffffu, sum, o);
        sq  += __shfl_xor_sync(0xffffffffu, sq,  o);
    }
    float mean = sum * (1.0f / CDIM);
    float var  = sq * (1.0f / CDIM) - mean * mean;
    float rstd = rsqrtf(var + 1e-5f);

    float4 w0 = ((const float4*)w)[lane];
    float4 w1 = ((const float4*)w)[lane + 32];
    float4 b0 = ((const float4*)b)[lane];
    float4 b1 = ((const float4*)b)[lane + 32];
    float4 o0, o1;
    o0.x = (a.x - mean) * rstd * w0.x + b0.x;
    o0.y = (a.y - mean) * rstd * w0.y + b0.y;
    o0.z = (a.z - mean) * rstd * w0.z + b0.z;
    o0.w = (a.w - mean) * rstd * w0.w + b0.w;
    o1.x = (c.x - mean) * rstd * w1.x + b1.x;
    o1.y = (c.y - mean) * rstd * w1.y + b1.y;
    o1.z = (c.z - mean) * rstd * w1.z + b1.z;
    o1.w = (c.w - mean) * rstd * w1.w + b1.w;
    float4* op = (float4*)(out + (size_t)gwarp * CDIM);
    op[lane] = o0;
    op[lane + 32] = o1;
}

// ---------------- generic fp32 GEMM: C = act(scale * A @ W^T + bias) ----------------
// A: [M, K] row-major with leading dim lda (M from gridDim.y*64)
// W: [N, K] row-major compact
// C: [M, N] with leading dim ldc
__device__ __forceinline__ float gelu_exact(float x) {
    return 0.5f * x * (1.0f + erff(x * 0.70710678118654752f));
}

__global__ void gemm_kernel(const float* __restrict__ A, int lda,
                            const float* __restrict__ W,
                            const float* __restrict__ bias,
                            float* __restrict__ Cc, int ldc,
                            int K, float scale, int act)
{
    __shared__ float As[16][68];
    __shared__ float Bs[16][68];

    int tid = threadIdx.x;                 // 256 threads
    int m0 = blockIdx.y * 64;
    int n0 = blockIdx.x * 64;
    int lrow = tid >> 2;                   // 0..63
    int lk   = (tid & 3) << 2;             // 0,4,8,12
    const float* Aptr = A + (size_t)(m0 + lrow) * lda + lk;
    const float* Wptr = W + (size_t)(n0 + lrow) * K + lk;

    int ty = tid >> 4;                     // 0..15 (m)
    int tx = tid & 15;                     // 0..15 (n)

    float acc[4][4];
    #pragma unroll
    for (int i = 0; i < 4; i++)
        #pragma unroll
        for (int j = 0; j < 4; j++) acc[i][j] = 0.0f;

    for (int k0 = 0; k0 < K; k0 += 16) {
        float4 av = *(const float4*)(Aptr + k0);
        float4 wv = *(const float4*)(Wptr + k0);
        As[lk + 0][lrow] = av.x; As[lk + 1][lrow] = av.y;
        As[lk + 2][lrow] = av.z; As[lk + 3][lrow] = av.w;
        Bs[lk + 0][lrow] = wv.x; Bs[lk + 1][lrow] = wv.y;
        Bs[lk + 2][lrow] = wv.z; Bs[lk + 3][lrow] = wv.w;
        __syncthreads();
        #pragma unroll
        for (int kk = 0; kk < 16; kk++) {
            float4 a4 = *(const float4*)&As[kk][ty * 4];
            float4 b4 = *(const float4*)&Bs[kk][tx * 4];
            float af[4] = {a4.x, a4.y, a4.z, a4.w};
            float bf[4] = {b4.x, b4.y, b4.z, b4.w};
            #pragma unroll
            for (int i = 0; i < 4; i++)
                #pragma unroll
                for (int j = 0; j < 4; j++)
                    acc[i][j] = fmaf(af[i], bf[j], acc[i][j]);
        }
        __syncthreads();
    }

    float bi[4] = {0.f, 0.f, 0.f, 0.f};
    if (bias) {
        float4 bv = *(const float4*)&bias[n0 + tx * 4];
        bi[0] = bv.x; bi[1] = bv.y; bi[2] = bv.z; bi[3] = bv.w;
    }
    #pragma unroll
    for (int i = 0; i < 4; i++) {
        int row = m0 + ty * 4 + i;
        float4 o;
        float v0 = acc[i][0] * scale + bi[0];
        float v1 = acc[i][1] * scale + bi[1];
        float v2 = acc[i][2] * scale + bi[2];
        float v3 = acc[i][3] * scale + bi[3];
        if (act) { v0 = gelu_exact(v0); v1 = gelu_exact(v1); v2 = gelu_exact(v2); v3 = gelu_exact(v3); }
        o.x = v0; o.y = v1; o.z = v2; o.w = v3;
        *(float4*)&Cc[(size_t)row * ldc + n0 + tx * 4] = o;
    }
}

// ---------------- dual-direction flash attention ----------------
// dir=0: Q=qk(stream0), K=qk(stream1), V=v(stream1) -> m(stream0)  [softmax over s]
// dir=1: Q=qk(stream1), K=qk(stream0), V=v(stream0) -> m(stream1)  [softmax over l]
__global__ void attn_kernel(const float* __restrict__ qk, const float* __restrict__ v,
                            float* __restrict__ out)
{
    const int dir = blockIdx.z >> 1;
    const int bb  = blockIdx.z & 1;
    const int h   = blockIdx.y;
    const int q_base = dir * TOK + bb * SEQ;
    const int k_base = (dir ^ 1) * TOK + bb * SEQ;

    __shared__ float Ks[64][HDIM];
    __shared__ float Vs[64][HDIM];

    const int tid = threadIdx.x;                       // 128 threads
    const int qrow = blockIdx.x * 128 + tid;

    float q[HDIM];
    {
        const float4* qp = (const float4*)&qk[(size_t)(q_base + qrow) * CDIM + h * HDIM];
        #pragma unroll
        for (int i = 0; i < 8; i++) {
            float4 t = qp[i];
            q[4*i] = t.x; q[4*i+1] = t.y; q[4*i+2] = t.z; q[4*i+3] = t.w;
        }
    }
    float acc[HDIM];
    #pragma unroll
    for (int i = 0; i < HDIM; i++) acc[i] = 0.0f;
    float mi = -1e30f, li = 0.0f;

    for (int kt = 0; kt < SEQ; kt += 64) {
        #pragma unroll
        for (int i = 0; i < 4; i++) {
            int idx = tid + i * 128;          // 0..511 float4 slots
            int r = idx >> 3;
            int c = (idx & 7) << 2;
            size_t goff = (size_t)(k_base + kt + r) * CDIM + h * HDIM + c;
            *(float4*)&Ks[r][c] = *(const float4*)&qk[goff];
            *(float4*)&Vs[r][c] = *(const float4*)&v[goff];
        }
        __syncthreads();
        #pragma unroll 2
        for (int j = 0; j < 64; j++) {
            float s = 0.0f;
            #pragma unroll
            for (int d4 = 0; d4 < 8; d4++) {
                float4 kv = *(const float4*)&Ks[j][d4 * 4];
                s = fmaf(q[4*d4],   kv.x, s);
                s = fmaf(q[4*d4+1], kv.y, s);
                s = fmaf(q[4*d4+2], kv.z, s);
                s = fmaf(q[4*d4+3], kv.w, s);
            }
            if (__any_sync(0xffffffffu, s > mi)) {
                float mn = fmaxf(mi, s);
                float corr = __expf(mi - mn);
                float p = __expf(s - mn);
                li = li * corr + p;
                #pragma unroll
                for (int d4 = 0; d4 < 8; d4++) {
                    float4 vv = *(const float4*)&Vs[j][d4 * 4];
                    acc[4*d4]   = fmaf(acc[4*d4],   corr, p * vv.x);
                    acc[4*d4+1] = fmaf(acc[4*d4+1], corr, p * vv.y);
                    acc[4*d4+2] = fmaf(acc[4*d4+2], corr, p * vv.z);
                    acc[4*d4+3] = fmaf(acc[4*d4+3], corr, p * vv.w);
                }
                mi = mn;
            } else {
                float p = __expf(s - mi);
                li += p;
                #pragma unroll
                for (int d4 = 0; d4 < 8; d4++) {
                    float4 vv = *(const float4*)&Vs[j][d4 * 4];
                    acc[4*d4]   = fmaf(p, vv.x, acc[4*d4]);
                    acc[4*d4+1] = fmaf(p, vv.y, acc[4*d4+1]);
                    acc[4*d4+2] = fmaf(p, vv.z, acc[4*d4+2]);
                    acc[4*d4+3] = fmaf(p, vv.w, acc[4*d4+3]);
                }
            }
        }
        __syncthreads();
    }
    float inv = 1.0f / li;
    float4* op = (float4*)&out[(size_t)(q_base + qrow) * CDIM + h * HDIM];
    #pragma unroll
    for (int i = 0; i < 8; i++) {
        float4 t;
        t.x = acc[4*i] * inv; t.y = acc[4*i+1] * inv;
        t.z = acc[4*i+2] * inv; t.w = acc[4*i+3] * inv;
        op[i] = t;
    }
}

// ---------------- copy x into concat buffer (cols 0..255 of g_xm, ld=512) ----------------
__global__ void copyx_kernel(const float* __restrict__ x0, const float* __restrict__ x1,
                             float* __restrict__ xm)
{
    int idx = blockIdx.x * blockDim.x + threadIdx.x;   // float4 id
    if (idx >= TTOK * CDIM / 4) return;
    int tok = idx >> 6;             // CDIM/4 = 64 float4 per token
    int c4  = idx & 63;
    const float4* src = (const float4*)((tok < TOK) ? (x0 + (size_t)tok * CDIM)
                                                    : (x1 + (size_t)(tok - TOK) * CDIM));
    ((float4*)(xm + (size_t)tok * (2 * CDIM)))[c4] = src[c4];
}

// ---------------- final: out = x + gamma * LN(h2; ln2_w, ln2_b) ----------------
__global__ void final_kernel(const float* __restrict__ x0, const float* __restrict__ x1,
                             const float* __restrict__ h2, const float* __restrict__ gamma,
                             const float* __restrict__ w, const float* __restrict__ b,
                             float* __restrict__ out)
{
    int gwarp = (blockIdx.x * blockDim.x + threadIdx.x) >> 5;
    int lane = threadIdx.x & 31;
    if (gwarp >= TTOK) return;
    const float* x = (gwarp < TOK) ? (x0 + (size_t)gwarp * CDIM)
                                   : (x1 + (size_t)(gwarp - TOK) * CDIM);
    const float* hh = h2 + (size_t)gwarp * CDIM;

    float4 a = ((const float4*)hh)[lane];
    float4 c = ((const float4*)hh)[lane + 32];
    float sum = a.x + a.y + a.z + a.w + c.x + c.y + c.z + c.w;
    float sq  = a.x*a.x + a.y*a.y + a.z*a.z + a.w*a.w
              + c.x*c.x + c.y*c.y + c.z*c.z + c.w*c.w;
    #pragma unroll
    for (int o = 16; o; o >>= 1) {
        sum += __shfl_xor_sync(0xffffffffu, sum, o);
        sq  += __shfl_xor_sync(0xffffffffu, sq,  o);
    }
    float mean = sum * (1.0f / CDIM);
    float var  = sq * (1.0f / CDIM) - mean * mean;
    float rstd = rsqrtf(var + 1e-5f);

    float4 xa = ((const float4*)x)[lane];
    float4 xc = ((const float4*)x)[lane + 32];
    float4 w0 = ((const float4*)w)[lane];
    float4 w1 = ((const float4*)w)[lane + 32];
    float4 b0 = ((const float4*)b)[lane];
    float4 b1 = ((const float4*)b)[lane + 32];
    float4 g0 = ((const float4*)gamma)[lane];
    float4 g1 = ((const float4*)gamma)[lane + 32];

    float4 o0, o1;
    o0.x = xa.x + g0.x * ((a.x - mean) * rstd * w0.x + b0.x);
    o0.y = xa.y + g0.y * ((a.y - mean) * rstd * w0.y + b0.y);
    o0.z = xa.z + g0.z * ((a.z - mean) * rstd * w0.z + b0.z);
    o0.w = xa.w + g0.w * ((a.w - mean) * rstd * w0.w + b0.w);
    o1.x = xc.x + g1.x * ((c.x - mean) * rstd * w1.x + b1.x);
    o1.y = xc.y + g1.y * ((c.y - mean) * rstd * w1.y + b1.y);
    o1.z = xc.z + g1.z * ((c.z - mean) * rstd * w1.z + b1.z);
    o1.w = xc.w + g1.w * ((c.w - mean) * rstd * w1.w + b1.w);

    float4* op = (float4*)(out + (size_t)gwarp * CDIM);
    op[lane] = o0;
    op[lane + 32] = o1;
}

// ---------------- launch ----------------
extern "C" void kernel_launch(void* const* d_in, const int* in_sizes, int n_in,
                              void* d_out, int out_size)
{
    const float* x0      = (const float*)d_in[0];
    const float* x1      = (const float*)d_in[1];
    const float* qk_w    = (const float*)d_in[2];
    const float* v_w     = (const float*)d_in[3];
    const float* merge_w = (const float*)d_in[4];
    const float* ln1_w   = (const float*)d_in[5];
    const float* ln1_b   = (const float*)d_in[6];
    const float* ln2_w   = (const float*)d_in[7];
    const float* ln2_b   = (const float*)d_in[8];
    const float* fc1_w   = (const float*)d_in[9];
    const float* fc1_b   = (const float*)d_in[10];
    const float* fc2_w   = (const float*)d_in[11];
    const float* fc2_b   = (const float*)d_in[12];
    const float* gamma   = (const float*)d_in[13];
    float* out = (float*)d_out;

    float *n_, *qk_, *v_, *m_, *xm_, *h1_, *h2_;
    cudaGetSymbolAddress((void**)&n_,  g_n);
    cudaGetSymbolAddress((void**)&qk_, g_qk);
    cudaGetSymbolAddress((void**)&v_,  g_v);
    cudaGetSymbolAddress((void**)&m_,  g_m);
    cudaGetSymbolAddress((void**)&xm_, g_xm);
    cudaGetSymbolAddress((void**)&h1_, g_h1);
    cudaGetSymbolAddress((void**)&h2_, g_h2);

    // 1. LayerNorm both streams
    ln1_kernel<<<TTOK / 8, 256>>>(x0, x1, ln1_w, ln1_b, n_);

    // 2. qk & v projections (qk fused with scale 32^-0.25)
    dim3 gproj(CDIM / 64, TTOK / 64);
    gemm_kernel<<<gproj, 256>>>(n_, CDIM, qk_w, nullptr, qk_, CDIM, CDIM, QK_SCALE, 0);
    gemm_kernel<<<gproj, 256>>>(n_, CDIM, v_w,  nullptr, v_,  CDIM, CDIM, 1.0f,     0);

    // 3. dual-direction flash attention
    attn_kernel<<<dim3(SEQ / 128, HEADS, 4), 128>>>(qk_, v_, m_);

    // 4. build concat buffer: cols [0,256) = x, cols [256,512) = m @ merge_w^T
    copyx_kernel<<<(TTOK * CDIM / 4 + 255) / 256, 256>>>(x0, x1, xm_);
    gemm_kernel<<<gproj, 256>>>(m_, CDIM, merge_w, nullptr, xm_ + CDIM, 2 * CDIM, CDIM, 1.0f, 0);

    // 5. fc1 + exact GELU
    gemm_kernel<<<dim3(HID / 64, TTOK / 64), 256>>>(xm_, 2 * CDIM, fc1_w, fc1_b, h1_, HID, 2 * CDIM, 1.0f, 1);

    // 6. fc2
    gemm_kernel<<<dim3(CDIM / 64, TTOK / 64), 256>>>(h1_, HID, fc2_w, fc2_b, h2_, CDIM, HID, 1.0f, 0);

    // 7. residual + LN2 epilogue -> output
    final_kernel<<<TTOK / 8, 256>>>(x0, x1, h2_, gamma, ln2_w, ln2_b, out);
}

// round 3
// speedup vs baseline: 1.3829x; 1.3829x over previous
#include <cuda_runtime.h>
#include <math.h>
#include <stdint.h>

// Problem constants
#define BATCH 2
#define SEQ   2048
#define CDIM  256
#define HEADS 8
#define HDIM  32
#define TOK   4096          // tokens per stream (BATCH*SEQ)
#define TTOK  8192          // total tokens (both streams)
#define HID   1024

// qk scale: 32^-0.25 (applied to both sides in reference)
#define QK_SCALE 0.42044820762685725f

// ---------------- scratch (static device allocations) ----------------
__device__ float g_n [TTOK * CDIM];        // ln1 output
__device__ float g_qk[TTOK * CDIM];        // qk projection (scaled)
__device__ float g_v [TTOK * CDIM];        // v projection
__device__ float g_m [TTOK * CDIM];        // attention output
__device__ float g_xm[TTOK * 2 * CDIM];    // concat(x, m@merge_w^T), ld=512
__device__ float g_h1[TTOK * HID];         // fc1+gelu output
__device__ float g_h2[TTOK * CDIM];        // fc2 output

// ---------------- packed f32x2 helpers ----------------
typedef unsigned long long u64;
__device__ __forceinline__ u64 f2fma(u64 a, u64 b, u64 c) {
    u64 d; asm("fma.rn.f32x2 %0, %1, %2, %3;" : "=l"(d) : "l"(a), "l"(b), "l"(c)); return d;
}
__device__ __forceinline__ u64 f2mul(u64 a, u64 b) {
    u64 d; asm("mul.rn.f32x2 %0, %1, %2;" : "=l"(d) : "l"(a), "l"(b)); return d;
}
__device__ __forceinline__ u64 f2add(u64 a, u64 b) {
    u64 d; asm("add.rn.f32x2 %0, %1, %2;" : "=l"(d) : "l"(a), "l"(b)); return d;
}
__device__ __forceinline__ u64 f2pack(float x) {
    u64 d; asm("mov.b64 %0, {%1, %1};" : "=l"(d) : "f"(x)); return d;
}
__device__ __forceinline__ float f2lo(u64 a) {
    float lo, hi; asm("mov.b64 {%0, %1}, %2;" : "=f"(lo), "=f"(hi) : "l"(a)); return lo;
}
__device__ __forceinline__ float f2hi(u64 a) {
    float lo, hi; asm("mov.b64 {%0, %1}, %2;" : "=f"(lo), "=f"(hi) : "l"(a)); return hi;
}

// ---------------- LayerNorm (warp per token) ----------------
__global__ void ln1_kernel(const float* __restrict__ x0, const float* __restrict__ x1,
                           const float* __restrict__ w, const float* __restrict__ b,
                           float* __restrict__ out)
{
    int gwarp = (blockIdx.x * blockDim.x + threadIdx.x) >> 5;
    int lane = threadIdx.x & 31;
    if (gwarp >= TTOK) return;
    const float* x = (gwarp < TOK) ? (x0 + (size_t)gwarp * CDIM)
                                   : (x1 + (size_t)(gwarp - TOK) * CDIM);
    float4 a = ((const float4*)x)[lane];
    float4 c = ((const float4*)x)[lane + 32];
    float sum = a.x + a.y + a.z + a.w + c.x + c.y + c.z + c.w;
    float sq  = a.x*a.x + a.y*a.y + a.z*a.z + a.w*a.w
              + c.x*c.x + c.y*c.y + c.z*c.z + c.w*c.w;
    #pragma unroll
    for (int o = 16; o; o >>= 1) {
        sum += __shfl_xor_sync(0xffffffffu, sum, o);
        sq  += __shfl_xor_sync(0xffffffffu, sq,  o);
    }
    float mean = sum * (1.0f / CDIM);
    float var  = sq * (1.0f / CDIM) - mean * mean;
    float rstd = rsqrtf(var + 1e-5f);

    float4 w0 = ((const float4*)w)[lane];
    float4 w1 = ((const float4*)w)[lane + 32];
    float4 b0 = ((const float4*)b)[lane];
    float4 b1 = ((const float4*)b)[lane + 32];
    float4 o0, o1;
    o0.x = (a.x - mean) * rstd * w0.x + b0.x;
    o0.y = (a.y - mean) * rstd * w0.y + b0.y;
    o0.z = (a.z - mean) * rstd * w0.z + b0.z;
    o0.w = (a.w - mean) * rstd * w0.w + b0.w;
    o1.x = (c.x - mean) * rstd * w1.x + b1.x;
    o1.y = (c.y - mean) * rstd * w1.y + b1.y;
    o1.z = (c.z - mean) * rstd * w1.z + b1.z;
    o1.w = (c.w - mean) * rstd * w1.w + b1.w;
    float4* op = (float4*)(out + (size_t)gwarp * CDIM);
    op[lane] = o0;
    op[lane + 32] = o1;
}

__device__ __forceinline__ float gelu_exact(float x) {
    return 0.5f * x * (1.0f + erff(x * 0.70710678118654752f));
}

// ---------------- fp32 SIMT GEMM (kept for qk/v projections, precision) ----------------
__global__ void gemm_kernel(const float* __restrict__ A, int lda,
                            const float* __restrict__ W,
                            const float* __restrict__ bias,
                            float* __restrict__ Cc, int ldc,
                            int K, float scale, int act)
{
    __shared__ float As[16][68];
    __shared__ float Bs[16][68];

    int tid = threadIdx.x;                 // 256 threads
    int m0 = blockIdx.y * 64;
    int n0 = blockIdx.x * 64;
    int lrow = tid >> 2;                   // 0..63
    int lk   = (tid & 3) << 2;             // 0,4,8,12
    const float* Aptr = A + (size_t)(m0 + lrow) * lda + lk;
    const float* Wptr = W + (size_t)(n0 + lrow) * K + lk;

    int ty = tid >> 4;
    int tx = tid & 15;

    float acc[4][4];
    #pragma unroll
    for (int i = 0; i < 4; i++)
        #pragma unroll
        for (int j = 0; j < 4; j++) acc[i][j] = 0.0f;

    for (int k0 = 0; k0 < K; k0 += 16) {
        float4 av = *(const float4*)(Aptr + k0);
        float4 wv = *(const float4*)(Wptr + k0);
        As[lk + 0][lrow] = av.x; As[lk + 1][lrow] = av.y;
        As[lk + 2][lrow] = av.z; As[lk + 3][lrow] = av.w;
        Bs[lk + 0][lrow] = wv.x; Bs[lk + 1][lrow] = wv.y;
        Bs[lk + 2][lrow] = wv.z; Bs[lk + 3][lrow] = wv.w;
        __syncthreads();
        #pragma unroll
        for (int kk = 0; kk < 16; kk++) {
            float4 a4 = *(const float4*)&As[kk][ty * 4];
            float4 b4 = *(const float4*)&Bs[kk][tx * 4];
            float af[4] = {a4.x, a4.y, a4.z, a4.w};
            float bf[4] = {b4.x, b4.y, b4.z, b4.w};
            #pragma unroll
            for (int i = 0; i < 4; i++)
                #pragma unroll
                for (int j = 0; j < 4; j++)
                    acc[i][j] = fmaf(af[i], bf[j], acc[i][j]);
        }
        __syncthreads();
    }

    #pragma unroll
    for (int i = 0; i < 4; i++) {
        int row = m0 + ty * 4 + i;
        float4 o;
        o.x = acc[i][0] * scale;
        o.y = acc[i][1] * scale;
        o.z = acc[i][2] * scale;
        o.w = acc[i][3] * scale;
        *(float4*)&Cc[(size_t)row * ldc + n0 + tx * 4] = o;
    }
}

// ---------------- tf32 tensor-core GEMM: C = act(A @ W^T + bias) ----------------
// A: [M,K] lda; W: [N,K] compact; C: [M,N] ldc. Block tile 128x64, warp 32x32.
__device__ __forceinline__ float to_tf32(float x) {
    uint32_t u; asm("cvt.rna.tf32.f32 %0, %1;" : "=r"(u) : "f"(x));
    return __uint_as_float(u);
}

__device__ __forceinline__ void mma_tf32(float* c, const float* a, const float* b) {
    asm volatile(
        "mma.sync.aligned.m16n8k8.row.col.f32.tf32.tf32.f32 "
        "{%0,%1,%2,%3}, {%4,%5,%6,%7}, {%8,%9}, {%0,%1,%2,%3};"
        : "+f"(c[0]), "+f"(c[1]), "+f"(c[2]), "+f"(c[3])
        : "r"(__float_as_uint(a[0])), "r"(__float_as_uint(a[1])),
          "r"(__float_as_uint(a[2])), "r"(__float_as_uint(a[3])),
          "r"(__float_as_uint(b[0])), "r"(__float_as_uint(b[1])));
}

__global__ __launch_bounds__(256) void gemm_tf32(
    const float* __restrict__ A, int lda,
    const float* __restrict__ W,
    const float* __restrict__ bias,
    float* __restrict__ Cc, int ldc,
    int K, int act)
{
    __shared__ float As[128][36];
    __shared__ float Ws[64][36];

    int tid = threadIdx.x;
    int lane = tid & 31;
    int warp = tid >> 5;          // 0..7
    int warp_m = warp & 3;        // 0..3 -> 32 rows each
    int warp_n = warp >> 2;       // 0..1 -> 32 cols each
    int m0 = blockIdx.y * 128;
    int n0 = blockIdx.x * 64;

    int grp = lane >> 2;          // 0..7
    int tig = lane & 3;           // 0..3

    float acc[2][4][4];
    #pragma unroll
    for (int mt = 0; mt < 2; mt++)
        #pragma unroll
        for (int nt = 0; nt < 4; nt++)
            #pragma unroll
            for (int r = 0; r < 4; r++) acc[mt][nt][r] = 0.0f;

    for (int k0 = 0; k0 < K; k0 += 32) {
        // load A slab 128x32 (1024 float4, 4 per thread)
        #pragma unroll
        for (int i = 0; i < 4; i++) {
            int idx = tid + i * 256;
            int row = idx >> 3;
            int kc  = (idx & 7) << 2;
            float4 v = *(const float4*)&A[(size_t)(m0 + row) * lda + k0 + kc];
            As[row][kc + 0] = to_tf32(v.x);
            As[row][kc + 1] = to_tf32(v.y);
            As[row][kc + 2] = to_tf32(v.z);
            As[row][kc + 3] = to_tf32(v.w);
        }
        // load W slab 64x32 (512 float4, 2 per thread)
        #pragma unroll
        for (int i = 0; i < 2; i++) {
            int idx = tid + i * 256;
            int row = idx >> 3;
            int kc  = (idx & 7) << 2;
            float4 v = *(const float4*)&W[(size_t)(n0 + row) * K + k0 + kc];
            Ws[row][kc + 0] = to_tf32(v.x);
            Ws[row][kc + 1] = to_tf32(v.y);
            Ws[row][kc + 2] = to_tf32(v.z);
            Ws[row][kc + 3] = to_tf32(v.w);
        }
        __syncthreads();

        #pragma unroll
        for (int ks = 0; ks < 4; ks++) {
            int kb = ks * 8;
            float a[2][4];
            #pragma unroll
            for (int mt = 0; mt < 2; mt++) {
                int rb = warp_m * 32 + mt * 16;
                a[mt][0] = As[rb + grp    ][kb + tig];
                a[mt][1] = As[rb + grp + 8][kb + tig];
                a[mt][2] = As[rb + grp    ][kb + tig + 4];
                a[mt][3] = As[rb + grp + 8][kb + tig + 4];
            }
            float b[4][2];
            #pragma unroll
            for (int nt = 0; nt < 4; nt++) {
                int nb = warp_n * 32 + nt * 8 + grp;
                b[nt][0] = Ws[nb][kb + tig];
                b[nt][1] = Ws[nb][kb + tig + 4];
            }
            #pragma unroll
            for (int mt = 0; mt < 2; mt++)
                #pragma unroll
                for (int nt = 0; nt < 4; nt++)
                    mma_tf32(acc[mt][nt], a[mt], b[nt]);
        }
        __syncthreads();
    }

    // epilogue
    #pragma unroll
    for (int mt = 0; mt < 2; mt++) {
        #pragma unroll
        for (int nt = 0; nt < 4; nt++) {
            int r = m0 + warp_m * 32 + mt * 16 + grp;
            int c = n0 + warp_n * 32 + nt * 8 + tig * 2;
            float b0 = bias ? bias[c]     : 0.0f;
            float b1 = bias ? bias[c + 1] : 0.0f;
            float v0 = acc[mt][nt][0] + b0;
            float v1 = acc[mt][nt][1] + b1;
            float v2 = acc[mt][nt][2] + b0;
            float v3 = acc[mt][nt][3] + b1;
            if (act) { v0 = gelu_exact(v0); v1 = gelu_exact(v1);
                       v2 = gelu_exact(v2); v3 = gelu_exact(v3); }
            float2 p0 = make_float2(v0, v1);
            float2 p1 = make_float2(v2, v3);
            *(float2*)&Cc[(size_t)r * ldc + c]       = p0;
            *(float2*)&Cc[(size_t)(r + 8) * ldc + c] = p1;
        }
    }
}

// ---------------- dual-direction flash attention (2 q-rows/thread, f32x2) ----------------
// dir=0: Q=qk(stream0), K=qk(stream1), V=v(stream1) -> m(stream0)
// dir=1: Q=qk(stream1), K=qk(stream0), V=v(stream0) -> m(stream1)
__global__ __launch_bounds__(128, 2)
void attn_kernel(const float* __restrict__ qk, const float* __restrict__ v,
                 float* __restrict__ out)
{
    const int dir = blockIdx.z >> 1;
    const int bb  = blockIdx.z & 1;
    const int h   = blockIdx.y;
    const int q_base = dir * TOK + bb * SEQ;
    const int k_base = (dir ^ 1) * TOK + bb * SEQ;

    __shared__ float Ks[64][HDIM];
    __shared__ float Vs[64][HDIM];

    const int tid = threadIdx.x;                      // 128 threads
    const int qrow0 = blockIdx.x * 256 + tid;         // rows handled: qrow0, qrow0+128
    const int qrow1 = qrow0 + 128;

    u64 q0[16], q1[16], a0[16], a1[16];
    {
        const ulonglong2* qp0 = (const ulonglong2*)&qk[(size_t)(q_base + qrow0) * CDIM + h * HDIM];
        const ulonglong2* qp1 = (const ulonglong2*)&qk[(size_t)(q_base + qrow1) * CDIM + h * HDIM];
        #pragma unroll
        for (int i = 0; i < 8; i++) {
            ulonglong2 t0 = qp0[i]; q0[2*i] = t0.x; q0[2*i+1] = t0.y;
            ulonglong2 t1 = qp1[i]; q1[2*i] = t1.x; q1[2*i+1] = t1.y;
        }
    }
    #pragma unroll
    for (int i = 0; i < 16; i++) { a0[i] = 0ull; a1[i] = 0ull; }
    float m0 = -1e30f, l0 = 0.0f;
    float m1 = -1e30f, l1 = 0.0f;

    for (int kt = 0; kt < SEQ; kt += 64) {
        #pragma unroll
        for (int i = 0; i < 4; i++) {
            int idx = tid + i * 128;          // 0..511 float4 slots
            int r = idx >> 3;
            int c = (idx & 7) << 2;
            size_t goff = (size_t)(k_base + kt + r) * CDIM + h * HDIM + c;
            *(float4*)&Ks[r][c] = *(const float4*)&qk[goff];
            *(float4*)&Vs[r][c] = *(const float4*)&v[goff];
        }
        __syncthreads();
        for (int j = 0; j < 64; j++) {
            // ---- dot products (packed, 2 accums per row) ----
            u64 t[16];
            {
                const ulonglong2* kp = (const ulonglong2*)&Ks[j][0];
                #pragma unroll
                for (int i = 0; i < 8; i++) { ulonglong2 kk = kp[i]; t[2*i] = kk.x; t[2*i+1] = kk.y; }
            }
            u64 s0a = 0ull, s0b = 0ull, s1a = 0ull, s1b = 0ull;
            #pragma unroll
            for (int d = 0; d < 8; d++) {
                s0a = f2fma(q0[2*d],   t[2*d],   s0a);
                s0b = f2fma(q0[2*d+1], t[2*d+1], s0b);
                s1a = f2fma(q1[2*d],   t[2*d],   s1a);
                s1b = f2fma(q1[2*d+1], t[2*d+1], s1b);
            }
            u64 s0p = f2add(s0a, s0b);
            u64 s1p = f2add(s1a, s1b);
            float s0 = f2lo(s0p) + f2hi(s0p);
            float s1 = f2lo(s1p) + f2hi(s1p);

            // ---- load V tile row ----
            {
                const ulonglong2* vp = (const ulonglong2*)&Vs[j][0];
                #pragma unroll
                for (int i = 0; i < 8; i++) { ulonglong2 vv = vp[i]; t[2*i] = vv.x; t[2*i+1] = vv.y; }
            }

            // ---- row 0 online softmax ----
            if (__any_sync(0xffffffffu, s0 > m0)) {
                float mn = fmaxf(m0, s0);
                float corr = __expf(m0 - mn);
                float p = __expf(s0 - mn);
                l0 = l0 * corr + p;
                u64 cp = f2pack(corr), pp = f2pack(p);
                #pragma unroll
                for (int d = 0; d < 16; d++)
                    a0[d] = f2fma(a0[d], cp, f2mul(pp, t[d]));
                m0 = mn;
            } else {
                float p = __expf(s0 - m0);
                l0 += p;
                u64 pp = f2pack(p);
                #pragma unroll
                for (int d = 0; d < 16; d++)
                    a0[d] = f2fma(pp, t[d], a0[d]);
            }
            // ---- row 1 online softmax ----
            if (__any_sync(0xffffffffu, s1 > m1)) {
                float mn = fmaxf(m1, s1);
                float corr = __expf(m1 - mn);
                float p = __expf(s1 - mn);
                l1 = l1 * corr + p;
                u64 cp = f2pack(corr), pp = f2pack(p);
                #pragma unroll
                for (int d = 0; d < 16; d++)
                    a1[d] = f2fma(a1[d], cp, f2mul(pp, t[d]));
                m1 = mn;
            } else {
                float p = __expf(s1 - m1);
                l1 += p;
                u64 pp = f2pack(p);
                #pragma unroll
                for (int d = 0; d < 16; d++)
                    a1[d] = f2fma(pp, t[d], a1[d]);
            }
        }
        __syncthreads();
    }
    u64 i0 = f2pack(1.0f / l0);
    u64 i1 = f2pack(1.0f / l1);
    ulonglong2* op0 = (ulonglong2*)&out[(size_t)(q_base + qrow0) * CDIM + h * HDIM];
    ulonglong2* op1 = (ulonglong2*)&out[(size_t)(q_base + qrow1) * CDIM + h * HDIM];
    #pragma unroll
    for (int i = 0; i < 8; i++) {
        ulonglong2 w0, w1;
        w0.x = f2mul(a0[2*i], i0); w0.y = f2mul(a0[2*i+1], i0);
        w1.x = f2mul(a1[2*i], i1); w1.y = f2mul(a1[2*i+1], i1);
        op0[i] = w0;
        op1[i] = w1;
    }
}

// ---------------- copy x into concat buffer (cols 0..255 of g_xm, ld=512) ----------------
__global__ void copyx_kernel(const float* __restrict__ x0, const float* __restrict__ x1,
                             float* __restrict__ xm)
{
    int idx = blockIdx.x * blockDim.x + threadIdx.x;   // float4 id
    if (idx >= TTOK * CDIM / 4) return;
    int tok = idx >> 6;
    int c4  = idx & 63;
    const float4* src = (const float4*)((tok < TOK) ? (x0 + (size_t)tok * CDIM)
                                                    : (x1 + (size_t)(tok - TOK) * CDIM));
    ((float4*)(xm + (size_t)tok * (2 * CDIM)))[c4] = src[c4];
}

// ---------------- final: out = x + gamma * LN(h2; ln2_w, ln2_b) ----------------
__global__ void final_kernel(const float* __restrict__ x0, const float* __restrict__ x1,
                             const float* __restrict__ h2, const float* __restrict__ gamma,
                             const float* __restrict__ w, const float* __restrict__ b,
                             float* __restrict__ out)
{
    int gwarp = (blockIdx.x * blockDim.x + threadIdx.x) >> 5;
    int lane = threadIdx.x & 31;
    if (gwarp >= TTOK) return;
    const float* x = (gwarp < TOK) ? (x0 + (size_t)gwarp * CDIM)
                                   : (x1 + (size_t)(gwarp - TOK) * CDIM);
    const float* hh = h2 + (size_t)gwarp * CDIM;

    float4 a = ((const float4*)hh)[lane];
    float4 c = ((const float4*)hh)[lane + 32];
    float sum = a.x + a.y + a.z + a.w + c.x + c.y + c.z + c.w;
    float sq  = a.x*a.x + a.y*a.y + a.z*a.z + a.w*a.w
              + c.x*c.x + c.y*c.y + c.z*c.z + c.w*c.w;
    #pragma unroll
    for (int o = 16; o; o >>= 1) {
        sum += __shfl_xor_sync(0xffffffffu, sum, o);
        sq  += __shfl_xor_sync(0xffffffffu, sq,  o);
    }
    float mean = sum * (1.0f / CDIM);
    float var  = sq * (1.0f / CDIM) - mean * mean;
    float rstd = rsqrtf(var + 1e-5f);

    float4 xa = ((const float4*)x)[lane];
    float4 xc = ((const float4*)x)[lane + 32];
    float4 w0 = ((const float4*)w)[lane];
    float4 w1 = ((const float4*)w)[lane + 32];
    float4 b0 = ((const float4*)b)[lane];
    float4 b1 = ((const float4*)b)[lane + 32];
    float4 g0 = ((const float4*)gamma)[lane];
    float4 g1 = ((const float4*)gamma)[lane + 32];

    float4 o0, o1;
    o0.x = xa.x + g0.x * ((a.x - mean) * rstd * w0.x + b0.x);
    o0.y = xa.y + g0.y * ((a.y - mean) * rstd * w0.y + b0.y);
    o0.z = xa.z + g0.z * ((a.z - mean) * rstd * w0.z + b0.z);
    o0.w = xa.w + g0.w * ((a.w - mean) * rstd * w0.w + b0.w);
    o1.x = xc.x + g1.x * ((c.x - mean) * rstd * w1.x + b1.x);
    o1.y = xc.y + g1.y * ((c.y - mean) * rstd * w1.y + b1.y);
    o1.z = xc.z + g1.z * ((c.z - mean) * rstd * w1.z + b1.z);
    o1.w = xc.w + g1.w * ((c.w - mean) * rstd * w1.w + b1.w);

    float4* op = (float4*)(out + (size_t)gwarp * CDIM);
    op[lane] = o0;
    op[lane + 32] = o1;
}

// ---------------- launch ----------------
extern "C" void kernel_launch(void* const* d_in, const int* in_sizes, int n_in,
                              void* d_out, int out_size)
{
    const float* x0      = (const float*)d_in[0];
    const float* x1      = (const float*)d_in[1];
    const float* qk_w    = (const float*)d_in[2];
    const float* v_w     = (const float*)d_in[3];
    const float* merge_w = (const float*)d_in[4];
    const float* ln1_w   = (const float*)d_in[5];
    const float* ln1_b   = (const float*)d_in[6];
    const float* ln2_w   = (const float*)d_in[7];
    const float* ln2_b   = (const float*)d_in[8];
    const float* fc1_w   = (const float*)d_in[9];
    const float* fc1_b   = (const float*)d_in[10];
    const float* fc2_w   = (const float*)d_in[11];
    const float* fc2_b   = (const float*)d_in[12];
    const float* gamma   = (const float*)d_in[13];
    float* out = (float*)d_out;

    float *n_, *qk_, *v_, *m_, *xm_, *h1_, *h2_;
    cudaGetSymbolAddress((void**)&n_,  g_n);
    cudaGetSymbolAddress((void**)&qk_, g_qk);
    cudaGetSymbolAddress((void**)&v_,  g_v);
    cudaGetSymbolAddress((void**)&m_,  g_m);
    cudaGetSymbolAddress((void**)&xm_, g_xm);
    cudaGetSymbolAddress((void**)&h1_, g_h1);
    cudaGetSymbolAddress((void**)&h2_, g_h2);

    // 1. LayerNorm both streams
    ln1_kernel<<<TTOK / 8, 256>>>(x0, x1, ln1_w, ln1_b, n_);

    // 2. qk & v projections (fp32 SIMT, qk fused with scale 32^-0.25)
    dim3 gproj(CDIM / 64, TTOK / 64);
    gemm_kernel<<<gproj, 256>>>(n_, CDIM, qk_w, nullptr, qk_, CDIM, CDIM, QK_SCALE, 0);
    gemm_kernel<<<gproj, 256>>>(n_, CDIM, v_w,  nullptr, v_,  CDIM, CDIM, 1.0f,     0);

    // 3. dual-direction flash attention (2 rows/thread)
    attn_kernel<<<dim3(SEQ / 256, HEADS, 4), 128>>>(qk_, v_, m_);

    // 4. build concat buffer: cols [0,256) = x, cols [256,512) = m @ merge_w^T (tf32)
    copyx_kernel<<<(TTOK * CDIM / 4 + 255) / 256, 256>>>(x0, x1, xm_);
    gemm_tf32<<<dim3(CDIM / 64, TTOK / 128), 256>>>(m_, CDIM, merge_w, nullptr, xm_ + CDIM, 2 * CDIM, CDIM, 0);

    // 5. fc1 + exact GELU (tf32)
    gemm_tf32<<<dim3(HID / 64, TTOK / 128), 256>>>(xm_, 2 * CDIM, fc1_w, fc1_b, h1_, HID, 2 * CDIM, 1);

    // 6. fc2 (tf32)
    gemm_tf32<<<dim3(CDIM / 64, TTOK / 128), 256>>>(h1_, HID, fc2_w, fc2_b, h2_, CDIM, HID, 0);

    // 7. residual + LN2 epilogue -> output
    final_kernel<<<TTOK / 8, 256>>>(x0, x1, h2_, gamma, ln2_w, ln2_b, out);
}

// round 4
// speedup vs baseline: 1.7285x; 1.2499x over previous
#include <cuda_runtime.h>
#include <math.h>
#include <stdint.h>

// Problem constants
#define BATCH 2
#define SEQ   2048
#define CDIM  256
#define HEADS 8
#define HDIM  32
#define TOK   4096          // tokens per stream (BATCH*SEQ)
#define TTOK  8192          // total tokens (both streams)
#define HID   1024

// qk scale: 32^-0.25 (applied to both sides in reference)
#define QK_SCALE 0.42044820762685725f

// ---------------- scratch (static device allocations) ----------------
__device__ float g_n [TTOK * CDIM];        // ln1 output
__device__ float g_qk[TTOK * CDIM];        // qk projection (scaled)
__device__ float g_v [TTOK * CDIM];        // v projection
__device__ float g_m [TTOK * CDIM];        // attention output
__device__ float g_xm[TTOK * 2 * CDIM];    // concat(x, m@merge_w^T), ld=512
__device__ float g_h1[TTOK * HID];         // fc1+gelu output
__device__ float g_h2[TTOK * CDIM];        // fc2 output

// ---------------- packed f32x2 helpers ----------------
typedef unsigned long long u64;
__device__ __forceinline__ u64 f2fma(u64 a, u64 b, u64 c) {
    u64 d; asm("fma.rn.f32x2 %0, %1, %2, %3;" : "=l"(d) : "l"(a), "l"(b), "l"(c)); return d;
}
__device__ __forceinline__ u64 f2mul(u64 a, u64 b) {
    u64 d; asm("mul.rn.f32x2 %0, %1, %2;" : "=l"(d) : "l"(a), "l"(b)); return d;
}
__device__ __forceinline__ u64 f2add(u64 a, u64 b) {
    u64 d; asm("add.rn.f32x2 %0, %1, %2;" : "=l"(d) : "l"(a), "l"(b)); return d;
}
__device__ __forceinline__ u64 f2pack(float x) {
    u64 d; asm("mov.b64 %0, {%1, %1};" : "=l"(d) : "f"(x)); return d;
}
__device__ __forceinline__ float f2lo(u64 a) {
    float lo, hi; asm("mov.b64 {%0, %1}, %2;" : "=f"(lo), "=f"(hi) : "l"(a)); return lo;
}
__device__ __forceinline__ float f2hi(u64 a) {
    float lo, hi; asm("mov.b64 {%0, %1}, %2;" : "=f"(lo), "=f"(hi) : "l"(a)); return hi;
}

// ---------------- LayerNorm (warp per token) ----------------
__global__ void ln1_kernel(const float* __restrict__ x0, const float* __restrict__ x1,
                           const float* __restrict__ w, const float* __restrict__ b,
                           float* __restrict__ out)
{
    int gwarp = (blockIdx.x * blockDim.x + threadIdx.x) >> 5;
    int lane = threadIdx.x & 31;
    if (gwarp >= TTOK) return;
    const float* x = (gwarp < TOK) ? (x0 + (size_t)gwarp * CDIM)
                                   : (x1 + (size_t)(gwarp - TOK) * CDIM);
    float4 a = ((const float4*)x)[lane];
    float4 c = ((const float4*)x)[lane + 32];
    float sum = a.x + a.y + a.z + a.w + c.x + c.y + c.z + c.w;
    float sq  = a.x*a.x + a.y*a.y + a.z*a.z + a.w*a.w
              + c.x*c.x + c.y*c.y + c.z*c.z + c.w*c.w;
    #pragma unroll
    for (int o = 16; o; o >>= 1) {
        sum += __shfl_xor_sync(0xffffffffu, sum, o);
        sq  += __shfl_xor_sync(0xffffffffu, sq,  o);
    }
    float mean = sum * (1.0f / CDIM);
    float var  = sq * (1.0f / CDIM) - mean * mean;
    float rstd = rsqrtf(var + 1e-5f);

    float4 w0 = ((const float4*)w)[lane];
    float4 w1 = ((const float4*)w)[lane + 32];
    float4 b0 = ((const float4*)b)[lane];
    float4 b1 = ((const float4*)b)[lane + 32];
    float4 o0, o1;
    o0.x = (a.x - mean) * rstd * w0.x + b0.x;
    o0.y = (a.y - mean) * rstd * w0.y + b0.y;
    o0.z = (a.z - mean) * rstd * w0.z + b0.z;
    o0.w = (a.w - mean) * rstd * w0.w + b0.w;
    o1.x = (c.x - mean) * rstd * w1.x + b1.x;
    o1.y = (c.y - mean) * rstd * w1.y + b1.y;
    o1.z = (c.z - mean) * rstd * w1.z + b1.z;
    o1.w = (c.w - mean) * rstd * w1.w + b1.w;
    float4* op = (float4*)(out + (size_t)gwarp * CDIM);
    op[lane] = o0;
    op[lane + 32] = o1;
}

__device__ __forceinline__ float gelu_exact(float x) {
    return 0.5f * x * (1.0f + erff(x * 0.70710678118654752f));
}

// ---------------- fp32 SIMT GEMM w/ packed f32x2 (qk/v projections) ----------------
// C = scale * A @ W^T ;  A:[M,K] lda, W:[N,K], C:[M,N] ldc
__global__ void gemm_kernel(const float* __restrict__ A, int lda,
                            const float* __restrict__ W,
                            float* __restrict__ Cc, int ldc,
                            int K, float scale)
{
    __shared__ float As[16][68];
    __shared__ float Bs[16][68];

    int tid = threadIdx.x;                 // 256 threads
    int m0 = blockIdx.y * 64;
    int n0 = blockIdx.x * 64;
    int lrow = tid >> 2;                   // 0..63
    int lk   = (tid & 3) << 2;             // 0,4,8,12
    const float* Aptr = A + (size_t)(m0 + lrow) * lda + lk;
    const float* Wptr = W + (size_t)(n0 + lrow) * K + lk;

    int ty = tid >> 4;
    int tx = tid & 15;

    u64 acc2[4][2];
    #pragma unroll
    for (int i = 0; i < 4; i++) { acc2[i][0] = 0ull; acc2[i][1] = 0ull; }

    for (int k0 = 0; k0 < K; k0 += 16) {
        float4 av = *(const float4*)(Aptr + k0);
        float4 wv = *(const float4*)(Wptr + k0);
        As[lk + 0][lrow] = av.x; As[lk + 1][lrow] = av.y;
        As[lk + 2][lrow] = av.z; As[lk + 3][lrow] = av.w;
        Bs[lk + 0][lrow] = wv.x; Bs[lk + 1][lrow] = wv.y;
        Bs[lk + 2][lrow] = wv.z; Bs[lk + 3][lrow] = wv.w;
        __syncthreads();
        #pragma unroll
        for (int kk = 0; kk < 16; kk++) {
            float4 a4 = *(const float4*)&As[kk][ty * 4];
            const u64* bp = (const u64*)&Bs[kk][tx * 4];
            u64 b0 = bp[0], b1 = bp[1];
            u64 a0 = f2pack(a4.x), a1 = f2pack(a4.y);
            u64 a2 = f2pack(a4.z), a3 = f2pack(a4.w);
            acc2[0][0] = f2fma(a0, b0, acc2[0][0]);
            acc2[0][1] = f2fma(a0, b1, acc2[0][1]);
            acc2[1][0] = f2fma(a1, b0, acc2[1][0]);
            acc2[1][1] = f2fma(a1, b1, acc2[1][1]);
            acc2[2][0] = f2fma(a2, b0, acc2[2][0]);
            acc2[2][1] = f2fma(a2, b1, acc2[2][1]);
            acc2[3][0] = f2fma(a3, b0, acc2[3][0]);
            acc2[3][1] = f2fma(a3, b1, acc2[3][1]);
        }
        __syncthreads();
    }

    u64 sp = f2pack(scale);
    #pragma unroll
    for (int i = 0; i < 4; i++) {
        int row = m0 + ty * 4 + i;
        u64 v0 = f2mul(acc2[i][0], sp);
        u64 v1 = f2mul(acc2[i][1], sp);
        float4 o;
        o.x = f2lo(v0); o.y = f2hi(v0);
        o.z = f2lo(v1); o.w = f2hi(v1);
        *(float4*)&Cc[(size_t)row * ldc + n0 + tx * 4] = o;
    }
}

// ---------------- tf32 tensor-core GEMM: C = act(A @ W^T + bias) ----------------
__device__ __forceinline__ float to_tf32(float x) {
    uint32_t u; asm("cvt.rna.tf32.f32 %0, %1;" : "=r"(u) : "f"(x));
    return __uint_as_float(u);
}

__device__ __forceinline__ void mma_tf32(float* c, const float* a, const float* b) {
    asm volatile(
        "mma.sync.aligned.m16n8k8.row.col.f32.tf32.tf32.f32 "
        "{%0,%1,%2,%3}, {%4,%5,%6,%7}, {%8,%9}, {%0,%1,%2,%3};"
        : "+f"(c[0]), "+f"(c[1]), "+f"(c[2]), "+f"(c[3])
        : "r"(__float_as_uint(a[0])), "r"(__float_as_uint(a[1])),
          "r"(__float_as_uint(a[2])), "r"(__float_as_uint(a[3])),
          "r"(__float_as_uint(b[0])), "r"(__float_as_uint(b[1])));
}

__global__ __launch_bounds__(256) void gemm_tf32(
    const float* __restrict__ A, int lda,
    const float* __restrict__ W,
    const float* __restrict__ bias,
    float* __restrict__ Cc, int ldc,
    int K, int act)
{
    __shared__ float As[128][36];
    __shared__ float Ws[64][36];

    int tid = threadIdx.x;
    int lane = tid & 31;
    int warp = tid >> 5;          // 0..7
    int warp_m = warp & 3;        // 0..3 -> 32 rows each
    int warp_n = warp >> 2;       // 0..1 -> 32 cols each
    int m0 = blockIdx.y * 128;
    int n0 = blockIdx.x * 64;

    int grp = lane >> 2;          // 0..7
    int tig = lane & 3;           // 0..3

    float acc[2][4][4];
    #pragma unroll
    for (int mt = 0; mt < 2; mt++)
        #pragma unroll
        for (int nt = 0; nt < 4; nt++)
            #pragma unroll
            for (int r = 0; r < 4; r++) acc[mt][nt][r] = 0.0f;

    for (int k0 = 0; k0 < K; k0 += 32) {
        #pragma unroll
        for (int i = 0; i < 4; i++) {
            int idx = tid + i * 256;
            int row = idx >> 3;
            int kc  = (idx & 7) << 2;
            float4 v = *(const float4*)&A[(size_t)(m0 + row) * lda + k0 + kc];
            As[row][kc + 0] = to_tf32(v.x);
            As[row][kc + 1] = to_tf32(v.y);
            As[row][kc + 2] = to_tf32(v.z);
            As[row][kc + 3] = to_tf32(v.w);
        }
        #pragma unroll
        for (int i = 0; i < 2; i++) {
            int idx = tid + i * 256;
            int row = idx >> 3;
            int kc  = (idx & 7) << 2;
            float4 v = *(const float4*)&W[(size_t)(n0 + row) * K + k0 + kc];
            Ws[row][kc + 0] = to_tf32(v.x);
            Ws[row][kc + 1] = to_tf32(v.y);
            Ws[row][kc + 2] = to_tf32(v.z);
            Ws[row][kc + 3] = to_tf32(v.w);
        }
        __syncthreads();

        #pragma unroll
        for (int ks = 0; ks < 4; ks++) {
            int kb = ks * 8;
            float a[2][4];
            #pragma unroll
            for (int mt = 0; mt < 2; mt++) {
                int rb = warp_m * 32 + mt * 16;
                a[mt][0] = As[rb + grp    ][kb + tig];
                a[mt][1] = As[rb + grp + 8][kb + tig];
                a[mt][2] = As[rb + grp    ][kb + tig + 4];
                a[mt][3] = As[rb + grp + 8][kb + tig + 4];
            }
            float b[4][2];
            #pragma unroll
            for (int nt = 0; nt < 4; nt++) {
                int nb = warp_n * 32 + nt * 8 + grp;
                b[nt][0] = Ws[nb][kb + tig];
                b[nt][1] = Ws[nb][kb + tig + 4];
            }
            #pragma unroll
            for (int mt = 0; mt < 2; mt++)
                #pragma unroll
                for (int nt = 0; nt < 4; nt++)
                    mma_tf32(acc[mt][nt], a[mt], b[nt]);
        }
        __syncthreads();
    }

    #pragma unroll
    for (int mt = 0; mt < 2; mt++) {
        #pragma unroll
        for (int nt = 0; nt < 4; nt++) {
            int r = m0 + warp_m * 32 + mt * 16 + grp;
            int c = n0 + warp_n * 32 + nt * 8 + tig * 2;
            float b0 = bias ? bias[c]     : 0.0f;
            float b1 = bias ? bias[c + 1] : 0.0f;
            float v0 = acc[mt][nt][0] + b0;
            float v1 = acc[mt][nt][1] + b1;
            float v2 = acc[mt][nt][2] + b0;
            float v3 = acc[mt][nt][3] + b1;
            if (act) { v0 = gelu_exact(v0); v1 = gelu_exact(v1);
                       v2 = gelu_exact(v2); v3 = gelu_exact(v3); }
            float2 p0 = make_float2(v0, v1);
            float2 p1 = make_float2(v2, v3);
            *(float2*)&Cc[(size_t)r * ldc + c]       = p0;
            *(float2*)&Cc[(size_t)(r + 8) * ldc + c] = p1;
        }
    }
}

// ---------------- dual-direction flash attention ----------------
// Chunked online softmax: 16 independent dots -> 1 rescale -> 16 exps -> 16 PV updates.
// dir=0: Q=qk(stream0), K=qk(stream1), V=v(stream1) -> m(stream0)
// dir=1: Q=qk(stream1), K=qk(stream0), V=v(stream0) -> m(stream1)
#define CHUNK 16
__global__ __launch_bounds__(128, 2)
void attn_kernel(const float* __restrict__ qk, const float* __restrict__ v,
                 float* __restrict__ out)
{
    const int dir = blockIdx.z >> 1;
    const int bb  = blockIdx.z & 1;
    const int h   = blockIdx.y;
    const int q_base = dir * TOK + bb * SEQ;
    const int k_base = (dir ^ 1) * TOK + bb * SEQ;

    __shared__ float Ks[64][HDIM];
    __shared__ float Vs[64][HDIM];

    const int tid = threadIdx.x;                      // 128 threads
    const int qrow0 = blockIdx.x * 256 + tid;         // rows: qrow0, qrow0+128
    const int qrow1 = qrow0 + 128;

    u64 q0[16], q1[16], a0[16], a1[16];
    {
        const ulonglong2* qp0 = (const ulonglong2*)&qk[(size_t)(q_base + qrow0) * CDIM + h * HDIM];
        const ulonglong2* qp1 = (const ulonglong2*)&qk[(size_t)(q_base + qrow1) * CDIM + h * HDIM];
        #pragma unroll
        for (int i = 0; i < 8; i++) {
            ulonglong2 t0 = qp0[i]; q0[2*i] = t0.x; q0[2*i+1] = t0.y;
            ulonglong2 t1 = qp1[i]; q1[2*i] = t1.x; q1[2*i+1] = t1.y;
        }
    }
    #pragma unroll
    for (int i = 0; i < 16; i++) { a0[i] = 0ull; a1[i] = 0ull; }
    float m0 = -1e30f, l0 = 0.0f;
    float m1 = -1e30f, l1 = 0.0f;

    for (int kt = 0; kt < SEQ; kt += 64) {
        #pragma unroll
        for (int i = 0; i < 4; i++) {
            int idx = tid + i * 128;          // 512 float4 slots
            int r = idx >> 3;
            int c = (idx & 7) << 2;
            size_t goff = (size_t)(k_base + kt + r) * CDIM + h * HDIM + c;
            *(float4*)&Ks[r][c] = *(const float4*)&qk[goff];
            *(float4*)&Vs[r][c] = *(const float4*)&v[goff];
        }
        __syncthreads();

        for (int cch = 0; cch < 64 / CHUNK; cch++) {
            float s0[CHUNK], s1[CHUNK];
            // ---- 16 independent dot products for both rows ----
            #pragma unroll
            for (int jj = 0; jj < CHUNK; jj++) {
                const ulonglong2* kp = (const ulonglong2*)&Ks[cch * CHUNK + jj][0];
                u64 dA0 = 0ull, dA1 = 0ull, dB0 = 0ull, dB1 = 0ull;
                #pragma unroll
                for (int i = 0; i < 8; i += 2) {
                    ulonglong2 k0 = kp[i];
                    ulonglong2 k1 = kp[i + 1];
                    dA0 = f2fma(q0[2*i],   k0.x, dA0);
                    dA1 = f2fma(q0[2*i+1], k0.y, dA1);
                    dB0 = f2fma(q1[2*i],   k0.x, dB0);
                    dB1 = f2fma(q1[2*i+1], k0.y, dB1);
                    dA0 = f2fma(q0[2*i+2], k1.x, dA0);
                    dA1 = f2fma(q0[2*i+3], k1.y, dA1);
                    dB0 = f2fma(q1[2*i+2], k1.x, dB0);
                    dB1 = f2fma(q1[2*i+3], k1.y, dB1);
                }
                u64 dA = f2add(dA0, dA1);
                u64 dB = f2add(dB0, dB1);
                s0[jj] = f2lo(dA) + f2hi(dA);
                s1[jj] = f2lo(dB) + f2hi(dB);
            }
            // ---- chunk max (tree) ----
            float t0[CHUNK / 2], t1[CHUNK / 2];
            #pragma unroll
            for (int i = 0; i < CHUNK / 2; i++) {
                t0[i] = fmaxf(s0[2*i], s0[2*i+1]);
                t1[i] = fmaxf(s1[2*i], s1[2*i+1]);
            }
            #pragma unroll
            for (int w = CHUNK / 4; w >= 1; w >>= 1)
                #pragma unroll
                for (int i = 0; i < w; i++) {
                    t0[i] = fmaxf(t0[i], t0[i + w]);
                    t1[i] = fmaxf(t1[i], t1[i + w]);
                }
            // ---- single rescale per chunk (branch-free) ----
            float mn0 = fmaxf(m0, t0[0]);
            float mn1 = fmaxf(m1, t1[0]);
            float corr0 = __expf(m0 - mn0);
            float corr1 = __expf(m1 - mn1);
            m0 = mn0; m1 = mn1;
            l0 *= corr0; l1 *= corr1;
            u64 cp0 = f2pack(corr0), cp1 = f2pack(corr1);
            #pragma unroll
            for (int d = 0; d < 16; d++) {
                a0[d] = f2mul(a0[d], cp0);
                a1[d] = f2mul(a1[d], cp1);
            }
            // ---- 16 independent exps ----
            float ps0 = 0.0f, ps1 = 0.0f;
            #pragma unroll
            for (int jj = 0; jj < CHUNK; jj++) {
                s0[jj] = __expf(s0[jj] - m0); ps0 += s0[jj];
                s1[jj] = __expf(s1[jj] - m1); ps1 += s1[jj];
            }
            l0 += ps0; l1 += ps1;
            // ---- PV rank-1 updates ----
            #pragma unroll
            for (int jj = 0; jj < CHUNK; jj++) {
                const ulonglong2* vp = (const ulonglong2*)&Vs[cch * CHUNK + jj][0];
                u64 p0 = f2pack(s0[jj]), p1 = f2pack(s1[jj]);
                #pragma unroll
                for (int i = 0; i < 8; i++) {
                    ulonglong2 vv = vp[i];
                    a0[2*i]   = f2fma(p0, vv.x, a0[2*i]);
                    a0[2*i+1] = f2fma(p0, vv.y, a0[2*i+1]);
                    a1[2*i]   = f2fma(p1, vv.x, a1[2*i]);
                    a1[2*i+1] = f2fma(p1, vv.y, a1[2*i+1]);
                }
            }
        }
        __syncthreads();
    }
    u64 i0 = f2pack(1.0f / l0);
    u64 i1 = f2pack(1.0f / l1);
    ulonglong2* op0 = (ulonglong2*)&out[(size_t)(q_base + qrow0) * CDIM + h * HDIM];
    ulonglong2* op1 = (ulonglong2*)&out[(size_t)(q_base + qrow1) * CDIM + h * HDIM];
    #pragma unroll
    for (int i = 0; i < 8; i++) {
        ulonglong2 w0, w1;
        w0.x = f2mul(a0[2*i], i0); w0.y = f2mul(a0[2*i+1], i0);
        w1.x = f2mul(a1[2*i], i1); w1.y = f2mul(a1[2*i+1], i1);
        op0[i] = w0;
        op1[i] = w1;
    }
}

// ---------------- copy x into concat buffer (cols 0..255 of g_xm, ld=512) ----------------
__global__ void copyx_kernel(const float* __restrict__ x0, const float* __restrict__ x1,
                             float* __restrict__ xm)
{
    int idx = blockIdx.x * blockDim.x + threadIdx.x;   // float4 id
    if (idx >= TTOK * CDIM / 4) return;
    int tok = idx >> 6;
    int c4  = idx & 63;
    const float4* src = (const float4*)((tok < TOK) ? (x0 + (size_t)tok * CDIM)
                                                    : (x1 + (size_t)(tok - TOK) * CDIM));
    ((float4*)(xm + (size_t)tok * (2 * CDIM)))[c4] = src[c4];
}

// ---------------- final: out = x + gamma * LN(h2; ln2_w, ln2_b) ----------------
__global__ void final_kernel(const float* __restrict__ x0, const float* __restrict__ x1,
                             const float* __restrict__ h2, const float* __restrict__ gamma,
                             const float* __restrict__ w, const float* __restrict__ b,
                             float* __restrict__ out)
{
    int gwarp = (blockIdx.x * blockDim.x + threadIdx.x) >> 5;
    int lane = threadIdx.x & 31;
    if (gwarp >= TTOK) return;
    const float* x = (gwarp < TOK) ? (x0 + (size_t)gwarp * CDIM)
                                   : (x1 + (size_t)(gwarp - TOK) * CDIM);
    const float* hh = h2 + (size_t)gwarp * CDIM;

    float4 a = ((const float4*)hh)[lane];
    float4 c = ((const float4*)hh)[lane + 32];
    float sum = a.x + a.y + a.z + a.w + c.x + c.y + c.z + c.w;
    float sq  = a.x*a.x + a.y*a.y + a.z*a.z + a.w*a.w
              + c.x*c.x + c.y*c.y + c.z*c.z + c.w*c.w;
    #pragma unroll
    for (int o = 16; o; o >>= 1) {
        sum += __shfl_xor_sync(0xffffffffu, sum, o);
        sq  += __shfl_xor_sync(0xffffffffu, sq,  o);
    }
    float mean = sum * (1.0f / CDIM);
    float var  = sq * (1.0f / CDIM) - mean * mean;
    float rstd = rsqrtf(var + 1e-5f);

    float4 xa = ((const float4*)x)[lane];
    float4 xc = ((const float4*)x)[lane + 32];
    float4 w0 = ((const float4*)w)[lane];
    float4 w1 = ((const float4*)w)[lane + 32];
    float4 b0 = ((const float4*)b)[lane];
    float4 b1 = ((const float4*)b)[lane + 32];
    float4 g0 = ((const float4*)gamma)[lane];
    float4 g1 = ((const float4*)gamma)[lane + 32];

    float4 o0, o1;
    o0.x = xa.x + g0.x * ((a.x - mean) * rstd * w0.x + b0.x);
    o0.y = xa.y + g0.y * ((a.y - mean) * rstd * w0.y + b0.y);
    o0.z = xa.z + g0.z * ((a.z - mean) * rstd * w0.z + b0.z);
    o0.w = xa.w + g0.w * ((a.w - mean) * rstd * w0.w + b0.w);
    o1.x = xc.x + g1.x * ((c.x - mean) * rstd * w1.x + b1.x);
    o1.y = xc.y + g1.y * ((c.y - mean) * rstd * w1.y + b1.y);
    o1.z = xc.z + g1.z * ((c.z - mean) * rstd * w1.z + b1.z);
    o1.w = xc.w + g1.w * ((c.w - mean) * rstd * w1.w + b1.w);

    float4* op = (float4*)(out + (size_t)gwarp * CDIM);
    op[lane] = o0;
    op[lane + 32] = o1;
}

// ---------------- launch ----------------
extern "C" void kernel_launch(void* const* d_in, const int* in_sizes, int n_in,
                              void* d_out, int out_size)
{
    const float* x0      = (const float*)d_in[0];
    const float* x1      = (const float*)d_in[1];
    const float* qk_w    = (const float*)d_in[2];
    const float* v_w     = (const float*)d_in[3];
    const float* merge_w = (const float*)d_in[4];
    const float* ln1_w   = (const float*)d_in[5];
    const float* ln1_b   = (const float*)d_in[6];
    const float* ln2_w   = (const float*)d_in[7];
    const float* ln2_b   = (const float*)d_in[8];
    const float* fc1_w   = (const float*)d_in[9];
    const float* fc1_b   = (const float*)d_in[10];
    const float* fc2_w   = (const float*)d_in[11];
    const float* fc2_b   = (const float*)d_in[12];
    const float* gamma   = (const float*)d_in[13];
    float* out = (float*)d_out;

    float *n_, *qk_, *v_, *m_, *xm_, *h1_, *h2_;
    cudaGetSymbolAddress((void**)&n_,  g_n);
    cudaGetSymbolAddress((void**)&qk_, g_qk);
    cudaGetSymbolAddress((void**)&v_,  g_v);
    cudaGetSymbolAddress((void**)&m_,  g_m);
    cudaGetSymbolAddress((void**)&xm_, g_xm);
    cudaGetSymbolAddress((void**)&h1_, g_h1);
    cudaGetSymbolAddress((void**)&h2_, g_h2);

    // 1. LayerNorm both streams
    ln1_kernel<<<TTOK / 8, 256>>>(x0, x1, ln1_w, ln1_b, n_);

    // 2. qk & v projections (fp32 SIMT f32x2, qk fused with scale 32^-0.25)
    dim3 gproj(CDIM / 64, TTOK / 64);
    gemm_kernel<<<gproj, 256>>>(n_, CDIM, qk_w, qk_, CDIM, CDIM, QK_SCALE);
    gemm_kernel<<<gproj, 256>>>(n_, CDIM, v_w,  v_,  CDIM, CDIM, 1.0f);

    // 3. dual-direction flash attention (chunked softmax, 2 rows/thread)
    attn_kernel<<<dim3(SEQ / 256, HEADS, 4), 128>>>(qk_, v_, m_);

    // 4. build concat buffer: cols [0,256) = x, cols [256,512) = m @ merge_w^T (tf32)
    copyx_kernel<<<(TTOK * CDIM / 4 + 255) / 256, 256>>>(x0, x1, xm_);
    gemm_tf32<<<dim3(CDIM / 64, TTOK / 128), 256>>>(m_, CDIM, merge_w, nullptr, xm_ + CDIM, 2 * CDIM, CDIM, 0);

    // 5. fc1 + exact GELU (tf32)
    gemm_tf32<<<dim3(HID / 64, TTOK / 128), 256>>>(xm_, 2 * CDIM, fc1_w, fc1_b, h1_, HID, 2 * CDIM, 1);

    // 6. fc2 (tf32)
    gemm_tf32<<<dim3(CDIM / 64, TTOK / 128), 256>>>(h1_, HID, fc2_w, fc2_b, h2_, CDIM, HID, 0);

    // 7. residual + LN2 epilogue -> output
    final_kernel<<<TTOK / 8, 256>>>(x0, x1, h2_, gamma, ln2_w, ln2_b, out);
}

// round 5
// speedup vs baseline: 1.8423x; 1.0658x over previous
#include <cuda_runtime.h>
#include <math.h>
#include <stdint.h>

// Problem constants
#define BATCH 2
#define SEQ   2048
#define CDIM  256
#define HEADS 8
#define HDIM  32
#define TOK   4096          // tokens per stream (BATCH*SEQ)
#define TTOK  8192          // total tokens (both streams)
#define HID   1024

#define SPLIT 4
#define NTASK (4 * HEADS * SEQ)        // (dir x batch) x heads x rows = 65536

// qk scale: 32^-0.25 (applied to both sides in reference)
#define QK_SCALE 0.42044820762685725f

// ---------------- scratch (static device allocations) ----------------
__device__ float g_n [TTOK * CDIM];        // ln1 output
__device__ float g_qk[TTOK * CDIM];        // qk projection (scaled)
__device__ float g_v [TTOK * CDIM];        // v projection
__device__ float g_m [TTOK * CDIM];        // attention output
__device__ float g_xm[TTOK * 2 * CDIM];    // concat(x, m@merge_w^T), ld=512
__device__ float g_h1[TTOK * HID];         // fc1+gelu output
__device__ float g_h2[TTOK * CDIM];        // fc2 output
// split-K attention partials
__device__ float g_pacc[SPLIT * NTASK * HDIM];
__device__ float g_pm  [SPLIT * NTASK];
__device__ float g_pl  [SPLIT * NTASK];

// ---------------- packed f32x2 helpers ----------------
typedef unsigned long long u64;
__device__ __forceinline__ u64 f2fma(u64 a, u64 b, u64 c) {
    u64 d; asm("fma.rn.f32x2 %0, %1, %2, %3;" : "=l"(d) : "l"(a), "l"(b), "l"(c)); return d;
}
__device__ __forceinline__ u64 f2mul(u64 a, u64 b) {
    u64 d; asm("mul.rn.f32x2 %0, %1, %2;" : "=l"(d) : "l"(a), "l"(b)); return d;
}
__device__ __forceinline__ u64 f2add(u64 a, u64 b) {
    u64 d; asm("add.rn.f32x2 %0, %1, %2;" : "=l"(d) : "l"(a), "l"(b)); return d;
}
__device__ __forceinline__ u64 f2pack(float x) {
    u64 d; asm("mov.b64 %0, {%1, %1};" : "=l"(d) : "f"(x)); return d;
}
__device__ __forceinline__ float f2lo(u64 a) {
    float lo, hi; asm("mov.b64 {%0, %1}, %2;" : "=f"(lo), "=f"(hi) : "l"(a)); return lo;
}
__device__ __forceinline__ float f2hi(u64 a) {
    float lo, hi; asm("mov.b64 {%0, %1}, %2;" : "=f"(lo), "=f"(hi) : "l"(a)); return hi;
}

// ---------------- LayerNorm (warp per token) ----------------
__global__ void ln1_kernel(const float* __restrict__ x0, const float* __restrict__ x1,
                           const float* __restrict__ w, const float* __restrict__ b,
                           float* __restrict__ out)
{
    int gwarp = (blockIdx.x * blockDim.x + threadIdx.x) >> 5;
    int lane = threadIdx.x & 31;
    if (gwarp >= TTOK) return;
    const float* x = (gwarp < TOK) ? (x0 + (size_t)gwarp * CDIM)
                                   : (x1 + (size_t)(gwarp - TOK) * CDIM);
    float4 a = ((const float4*)x)[lane];
    float4 c = ((const float4*)x)[lane + 32];
    float sum = a.x + a.y + a.z + a.w + c.x + c.y + c.z + c.w;
    float sq  = a.x*a.x + a.y*a.y + a.z*a.z + a.w*a.w
              + c.x*c.x + c.y*c.y + c.z*c.z + c.w*c.w;
    #pragma unroll
    for (int o = 16; o; o >>= 1) {
        sum += __shfl_xor_sync(0xffffffffu, sum, o);
        sq  += __shfl_xor_sync(0xffffffffu, sq,  o);
    }
    float mean = sum * (1.0f / CDIM);
    float var  = sq * (1.0f / CDIM) - mean * mean;
    float rstd = rsqrtf(var + 1e-5f);

    float4 w0 = ((const float4*)w)[lane];
    float4 w1 = ((const float4*)w)[lane + 32];
    float4 b0 = ((const float4*)b)[lane];
    float4 b1 = ((const float4*)b)[lane + 32];
    float4 o0, o1;
    o0.x = (a.x - mean) * rstd * w0.x + b0.x;
    o0.y = (a.y - mean) * rstd * w0.y + b0.y;
    o0.z = (a.z - mean) * rstd * w0.z + b0.z;
    o0.w = (a.w - mean) * rstd * w0.w + b0.w;
    o1.x = (c.x - mean) * rstd * w1.x + b1.x;
    o1.y = (c.y - mean) * rstd * w1.y + b1.y;
    o1.z = (c.z - mean) * rstd * w1.z + b1.z;
    o1.w = (c.w - mean) * rstd * w1.w + b1.w;
    float4* op = (float4*)(out + (size_t)gwarp * CDIM);
    op[lane] = o0;
    op[lane + 32] = o1;
}

__device__ __forceinline__ float gelu_exact(float x) {
    return 0.5f * x * (1.0f + erff(x * 0.70710678118654752f));
}

// ---------------- fp32 SIMT GEMM w/ packed f32x2 (qk/v projections) ----------------
__global__ void gemm_kernel(const float* __restrict__ A, int lda,
                            const float* __restrict__ W,
                            float* __restrict__ Cc, int ldc,
                            int K, float scale)
{
    __shared__ float As[16][68];
    __shared__ float Bs[16][68];

    int tid = threadIdx.x;                 // 256 threads
    int m0 = blockIdx.y * 64;
    int n0 = blockIdx.x * 64;
    int lrow = tid >> 2;                   // 0..63
    int lk   = (tid & 3) << 2;             // 0,4,8,12
    const float* Aptr = A + (size_t)(m0 + lrow) * lda + lk;
    const float* Wptr = W + (size_t)(n0 + lrow) * K + lk;

    int ty = tid >> 4;
    int tx = tid & 15;

    u64 acc2[4][2];
    #pragma unroll
    for (int i = 0; i < 4; i++) { acc2[i][0] = 0ull; acc2[i][1] = 0ull; }

    for (int k0 = 0; k0 < K; k0 += 16) {
        float4 av = *(const float4*)(Aptr + k0);
        float4 wv = *(const float4*)(Wptr + k0);
        As[lk + 0][lrow] = av.x; As[lk + 1][lrow] = av.y;
        As[lk + 2][lrow] = av.z; As[lk + 3][lrow] = av.w;
        Bs[lk + 0][lrow] = wv.x; Bs[lk + 1][lrow] = wv.y;
        Bs[lk + 2][lrow] = wv.z; Bs[lk + 3][lrow] = wv.w;
        __syncthreads();
        #pragma unroll
        for (int kk = 0; kk < 16; kk++) {
            float4 a4 = *(const float4*)&As[kk][ty * 4];
            const u64* bp = (const u64*)&Bs[kk][tx * 4];
            u64 b0 = bp[0], b1 = bp[1];
            u64 a0 = f2pack(a4.x), a1 = f2pack(a4.y);
            u64 a2 = f2pack(a4.z), a3 = f2pack(a4.w);
            acc2[0][0] = f2fma(a0, b0, acc2[0][0]);
            acc2[0][1] = f2fma(a0, b1, acc2[0][1]);
            acc2[1][0] = f2fma(a1, b0, acc2[1][0]);
            acc2[1][1] = f2fma(a1, b1, acc2[1][1]);
            acc2[2][0] = f2fma(a2, b0, acc2[2][0]);
            acc2[2][1] = f2fma(a2, b1, acc2[2][1]);
            acc2[3][0] = f2fma(a3, b0, acc2[3][0]);
            acc2[3][1] = f2fma(a3, b1, acc2[3][1]);
        }
        __syncthreads();
    }

    u64 sp = f2pack(scale);
    #pragma unroll
    for (int i = 0; i < 4; i++) {
        int row = m0 + ty * 4 + i;
        u64 v0 = f2mul(acc2[i][0], sp);
        u64 v1 = f2mul(acc2[i][1], sp);
        float4 o;
        o.x = f2lo(v0); o.y = f2hi(v0);
        o.z = f2lo(v1); o.w = f2hi(v1);
        *(float4*)&Cc[(size_t)row * ldc + n0 + tx * 4] = o;
    }
}

// ---------------- tf32 tensor-core GEMM: C = act(A @ W^T + bias) ----------------
__device__ __forceinline__ float to_tf32(float x) {
    uint32_t u; asm("cvt.rna.tf32.f32 %0, %1;" : "=r"(u) : "f"(x));
    return __uint_as_float(u);
}

__device__ __forceinline__ void mma_tf32(float* c, const float* a, const float* b) {
    asm volatile(
        "mma.sync.aligned.m16n8k8.row.col.f32.tf32.tf32.f32 "
        "{%0,%1,%2,%3}, {%4,%5,%6,%7}, {%8,%9}, {%0,%1,%2,%3};"
        : "+f"(c[0]), "+f"(c[1]), "+f"(c[2]), "+f"(c[3])
        : "r"(__float_as_uint(a[0])), "r"(__float_as_uint(a[1])),
          "r"(__float_as_uint(a[2])), "r"(__float_as_uint(a[3])),
          "r"(__float_as_uint(b[0])), "r"(__float_as_uint(b[1])));
}

__global__ __launch_bounds__(256) void gemm_tf32(
    const float* __restrict__ A, int lda,
    const float* __restrict__ W,
    const float* __restrict__ bias,
    float* __restrict__ Cc, int ldc,
    int K, int act)
{
    __shared__ float As[128][36];
    __shared__ float Ws[64][36];

    int tid = threadIdx.x;
    int lane = tid & 31;
    int warp = tid >> 5;          // 0..7
    int warp_m = warp & 3;
    int warp_n = warp >> 2;
    int m0 = blockIdx.y * 128;
    int n0 = blockIdx.x * 64;

    int grp = lane >> 2;          // 0..7
    int tig = lane & 3;           // 0..3

    float acc[2][4][4];
    #pragma unroll
    for (int mt = 0; mt < 2; mt++)
        #pragma unroll
        for (int nt = 0; nt < 4; nt++)
            #pragma unroll
            for (int r = 0; r < 4; r++) acc[mt][nt][r] = 0.0f;

    for (int k0 = 0; k0 < K; k0 += 32) {
        #pragma unroll
        for (int i = 0; i < 4; i++) {
            int idx = tid + i * 256;
            int row = idx >> 3;
            int kc  = (idx & 7) << 2;
            float4 v = *(const float4*)&A[(size_t)(m0 + row) * lda + k0 + kc];
            As[row][kc + 0] = to_tf32(v.x);
            As[row][kc + 1] = to_tf32(v.y);
            As[row][kc + 2] = to_tf32(v.z);
            As[row][kc + 3] = to_tf32(v.w);
        }
        #pragma unroll
        for (int i = 0; i < 2; i++) {
            int idx = tid + i * 256;
            int row = idx >> 3;
            int kc  = (idx & 7) << 2;
            float4 v = *(const float4*)&W[(size_t)(n0 + row) * K + k0 + kc];
            Ws[row][kc + 0] = to_tf32(v.x);
            Ws[row][kc + 1] = to_tf32(v.y);
            Ws[row][kc + 2] = to_tf32(v.z);
            Ws[row][kc + 3] = to_tf32(v.w);
        }
        __syncthreads();

        #pragma unroll
        for (int ks = 0; ks < 4; ks++) {
            int kb = ks * 8;
            float a[2][4];
            #pragma unroll
            for (int mt = 0; mt < 2; mt++) {
                int rb = warp_m * 32 + mt * 16;
                a[mt][0] = As[rb + grp    ][kb + tig];
                a[mt][1] = As[rb + grp + 8][kb + tig];
                a[mt][2] = As[rb + grp    ][kb + tig + 4];
                a[mt][3] = As[rb + grp + 8][kb + tig + 4];
            }
            float b[4][2];
            #pragma unroll
            for (int nt = 0; nt < 4; nt++) {
                int nb = warp_n * 32 + nt * 8 + grp;
                b[nt][0] = Ws[nb][kb + tig];
                b[nt][1] = Ws[nb][kb + tig + 4];
            }
            #pragma unroll
            for (int mt = 0; mt < 2; mt++)
                #pragma unroll
                for (int nt = 0; nt < 4; nt++)
                    mma_tf32(acc[mt][nt], a[mt], b[nt]);
        }
        __syncthreads();
    }

    #pragma unroll
    for (int mt = 0; mt < 2; mt++) {
        #pragma unroll
        for (int nt = 0; nt < 4; nt++) {
            int r = m0 + warp_m * 32 + mt * 16 + grp;
            int c = n0 + warp_n * 32 + nt * 8 + tig * 2;
            float b0 = bias ? bias[c]     : 0.0f;
            float b1 = bias ? bias[c + 1] : 0.0f;
            float v0 = acc[mt][nt][0] + b0;
            float v1 = acc[mt][nt][1] + b1;
            float v2 = acc[mt][nt][2] + b0;
            float v3 = acc[mt][nt][3] + b1;
            if (act) { v0 = gelu_exact(v0); v1 = gelu_exact(v1);
                       v2 = gelu_exact(v2); v3 = gelu_exact(v3); }
            float2 p0 = make_float2(v0, v1);
            float2 p1 = make_float2(v2, v3);
            *(float2*)&Cc[(size_t)r * ldc + c]       = p0;
            *(float2*)&Cc[(size_t)(r + 8) * ldc + c] = p1;
        }
    }
}

// ---------------- split-K dual-direction flash attention ----------------
// Each block: 256 q-rows (2/thread) x 512 keys -> partial (acc, m, l).
// blockIdx.x = qblk * SPLIT + split ; blockIdx.y = head ; blockIdx.z = combo (dir*2+bb)
#define CHUNK 16
#define KEYS_PER_SPLIT (SEQ / SPLIT)
__global__ __launch_bounds__(128, 2)
void attn_kernel(const float* __restrict__ qk, const float* __restrict__ v,
                 float* __restrict__ pacc, float* __restrict__ pm, float* __restrict__ pl)
{
    const int combo = blockIdx.z;
    const int dir = combo >> 1;
    const int bb  = combo & 1;
    const int h   = blockIdx.y;
    const int qblk  = blockIdx.x / SPLIT;
    const int split = blockIdx.x % SPLIT;
    const int q_base = dir * TOK + bb * SEQ;
    const int k_base = (dir ^ 1) * TOK + bb * SEQ;

    __shared__ float Ks[64][HDIM];
    __shared__ float Vs[64][HDIM];

    const int tid = threadIdx.x;                      // 128 threads
    const int qrow0 = qblk * 256 + tid;               // rows: qrow0, qrow0+128
    const int qrow1 = qrow0 + 128;

    u64 q0[16], q1[16], a0[16], a1[16];
    {
        const ulonglong2* qp0 = (const ulonglong2*)&qk[(size_t)(q_base + qrow0) * CDIM + h * HDIM];
        const ulonglong2* qp1 = (const ulonglong2*)&qk[(size_t)(q_base + qrow1) * CDIM + h * HDIM];
        #pragma unroll
        for (int i = 0; i < 8; i++) {
            ulonglong2 t0 = qp0[i]; q0[2*i] = t0.x; q0[2*i+1] = t0.y;
            ulonglong2 t1 = qp1[i]; q1[2*i] = t1.x; q1[2*i+1] = t1.y;
        }
    }
    #pragma unroll
    for (int i = 0; i < 16; i++) { a0[i] = 0ull; a1[i] = 0ull; }
    float m0 = -1e30f, l0 = 0.0f;
    float m1 = -1e30f, l1 = 0.0f;

    const int kt_beg = split * KEYS_PER_SPLIT;
    const int kt_end = kt_beg + KEYS_PER_SPLIT;
    for (int kt = kt_beg; kt < kt_end; kt += 64) {
        #pragma unroll
        for (int i = 0; i < 4; i++) {
            int idx = tid + i * 128;
            int r = idx >> 3;
            int c = (idx & 7) << 2;
            size_t goff = (size_t)(k_base + kt + r) * CDIM + h * HDIM + c;
            *(float4*)&Ks[r][c] = *(const float4*)&qk[goff];
            *(float4*)&Vs[r][c] = *(const float4*)&v[goff];
        }
        __syncthreads();

        for (int cch = 0; cch < 64 / CHUNK; cch++) {
            float s0[CHUNK], s1[CHUNK];
            #pragma unroll
            for (int jj = 0; jj < CHUNK; jj++) {
                const ulonglong2* kp = (const ulonglong2*)&Ks[cch * CHUNK + jj][0];
                u64 dA0 = 0ull, dA1 = 0ull, dB0 = 0ull, dB1 = 0ull;
                #pragma unroll
                for (int i = 0; i < 8; i += 2) {
                    ulonglong2 k0 = kp[i];
                    ulonglong2 k1 = kp[i + 1];
                    dA0 = f2fma(q0[2*i],   k0.x, dA0);
                    dA1 = f2fma(q0[2*i+1], k0.y, dA1);
                    dB0 = f2fma(q1[2*i],   k0.x, dB0);
                    dB1 = f2fma(q1[2*i+1], k0.y, dB1);
                    dA0 = f2fma(q0[2*i+2], k1.x, dA0);
                    dA1 = f2fma(q0[2*i+3], k1.y, dA1);
                    dB0 = f2fma(q1[2*i+2], k1.x, dB0);
                    dB1 = f2fma(q1[2*i+3], k1.y, dB1);
                }
                u64 dA = f2add(dA0, dA1);
                u64 dB = f2add(dB0, dB1);
                s0[jj] = f2lo(dA) + f2hi(dA);
                s1[jj] = f2lo(dB) + f2hi(dB);
            }
            // chunk max (tree)
            float t0[CHUNK / 2], t1[CHUNK / 2];
            #pragma unroll
            for (int i = 0; i < CHUNK / 2; i++) {
                t0[i] = fmaxf(s0[2*i], s0[2*i+1]);
                t1[i] = fmaxf(s1[2*i], s1[2*i+1]);
            }
            #pragma unroll
            for (int w = CHUNK / 4; w >= 1; w >>= 1)
                #pragma unroll
                for (int i = 0; i < w; i++) {
                    t0[i] = fmaxf(t0[i], t0[i + w]);
                    t1[i] = fmaxf(t1[i], t1[i + w]);
                }
            float mn0 = fmaxf(m0, t0[0]);
            float mn1 = fmaxf(m1, t1[0]);
            float corr0 = __expf(m0 - mn0);
            float corr1 = __expf(m1 - mn1);
            m0 = mn0; m1 = mn1;
            l0 *= corr0; l1 *= corr1;
            u64 cp0 = f2pack(corr0), cp1 = f2pack(corr1);
            #pragma unroll
            for (int d = 0; d < 16; d++) {
                a0[d] = f2mul(a0[d], cp0);
                a1[d] = f2mul(a1[d], cp1);
            }
            float ps0 = 0.0f, ps1 = 0.0f;
            #pragma unroll
            for (int jj = 0; jj < CHUNK; jj++) {
                s0[jj] = __expf(s0[jj] - m0); ps0 += s0[jj];
                s1[jj] = __expf(s1[jj] - m1); ps1 += s1[jj];
            }
            l0 += ps0; l1 += ps1;
            #pragma unroll
            for (int jj = 0; jj < CHUNK; jj++) {
                const ulonglong2* vp = (const ulonglong2*)&Vs[cch * CHUNK + jj][0];
                u64 p0 = f2pack(s0[jj]), p1 = f2pack(s1[jj]);
                #pragma unroll
                for (int i = 0; i < 8; i++) {
                    ulonglong2 vv = vp[i];
                    a0[2*i]   = f2fma(p0, vv.x, a0[2*i]);
                    a0[2*i+1] = f2fma(p0, vv.y, a0[2*i+1]);
                    a1[2*i]   = f2fma(p1, vv.x, a1[2*i]);
                    a1[2*i+1] = f2fma(p1, vv.y, a1[2*i+1]);
                }
            }
        }
        __syncthreads();
    }

    // write partials (unnormalized)
    const int task0 = (combo * HEADS + h) * SEQ + qrow0;
    const int task1 = task0 + 128;
    ulonglong2* pp0 = (ulonglong2*)&pacc[((size_t)split * NTASK + task0) * HDIM];
    ulonglong2* pp1 = (ulonglong2*)&pacc[((size_t)split * NTASK + task1) * HDIM];
    #pragma unroll
    for (int i = 0; i < 8; i++) {
        ulonglong2 w0, w1;
        w0.x = a0[2*i]; w0.y = a0[2*i+1];
        w1.x = a1[2*i]; w1.y = a1[2*i+1];
        pp0[i] = w0;
        pp1[i] = w1;
    }
    pm[(size_t)split * NTASK + task0] = m0;
    pm[(size_t)split * NTASK + task1] = m1;
    pl[(size_t)split * NTASK + task0] = l0;
    pl[(size_t)split * NTASK + task1] = l1;
}

// ---------------- split-K combine: one warp per task ----------------
__global__ void attn_combine_kernel(const float* __restrict__ pacc,
                                    const float* __restrict__ pm,
                                    const float* __restrict__ pl,
                                    float* __restrict__ out)
{
    int task = (blockIdx.x * blockDim.x + threadIdx.x) >> 5;
    int lane = threadIdx.x & 31;
    if (task >= NTASK) return;

    // decode task -> output location
    int row   = task & (SEQ - 1);
    int h     = (task >> 11) & (HEADS - 1);
    int combo = task >> 14;
    int dir = combo >> 1, bb = combo & 1;
    int q_base = dir * TOK + bb * SEQ;

    // lanes 0..SPLIT-1 read m/l, broadcast
    float ms = (lane < SPLIT) ? pm[(size_t)lane * NTASK + task] : -1e30f;
    float M = ms;
    #pragma unroll
    for (int o = SPLIT / 2; o; o >>= 1) M = fmaxf(M, __shfl_xor_sync(0xffffffffu, M, o));
    M = __shfl_sync(0xffffffffu, M, 0);

    float w = 0.0f;
    if (lane < SPLIT) {
        float ls = pl[(size_t)lane * NTASK + task];
        w = ls * __expf(ms - M);
    }
    float L = w;
    #pragma unroll
    for (int o = SPLIT / 2; o; o >>= 1) L += __shfl_xor_sync(0xffffffffu, L, o);
    L = __shfl_sync(0xffffffffu, L, 0);

    // each lane owns one of 32 dims
    float acc = 0.0f;
    #pragma unroll
    for (int s = 0; s < SPLIT; s++) {
        float es = __expf(__shfl_sync(0xffffffffu, ms, s) - M);
        acc += pacc[((size_t)s * NTASK + task) * HDIM + lane] * es;
    }
    out[(size_t)(q_base + row) * CDIM + h * HDIM + lane] = acc / L;
}

// ---------------- copy x into concat buffer (cols 0..255 of g_xm, ld=512) ----------------
__global__ void copyx_kernel(const float* __restrict__ x0, const float* __restrict__ x1,
                             float* __restrict__ xm)
{
    int idx = blockIdx.x * blockDim.x + threadIdx.x;
    if (idx >= TTOK * CDIM / 4) return;
    int tok = idx >> 6;
    int c4  = idx & 63;
    const float4* src = (const float4*)((tok < TOK) ? (x0 + (size_t)tok * CDIM)
                                                    : (x1 + (size_t)(tok - TOK) * CDIM));
    ((float4*)(xm + (size_t)tok * (2 * CDIM)))[c4] = src[c4];
}

// ---------------- final: out = x + gamma * LN(h2; ln2_w, ln2_b) ----------------
__global__ void final_kernel(const float* __restrict__ x0, const float* __restrict__ x1,
                             const float* __restrict__ h2, const float* __restrict__ gamma,
                             const float* __restrict__ w, const float* __restrict__ b,
                             float* __restrict__ out)
{
    int gwarp = (blockIdx.x * blockDim.x + threadIdx.x) >> 5;
    int lane = threadIdx.x & 31;
    if (gwarp >= TTOK) return;
    const float* x = (gwarp < TOK) ? (x0 + (size_t)gwarp * CDIM)
                                   : (x1 + (size_t)(gwarp - TOK) * CDIM);
    const float* hh = h2 + (size_t)gwarp * CDIM;

    float4 a = ((const float4*)hh)[lane];
    float4 c = ((const float4*)hh)[lane + 32];
    float sum = a.x + a.y + a.z + a.w + c.x + c.y + c.z + c.w;
    float sq  = a.x*a.x + a.y*a.y + a.z*a.z + a.w*a.w
              + c.x*c.x + c.y*c.y + c.z*c.z + c.w*c.w;
    #pragma unroll
    for (int o = 16; o; o >>= 1) {
        sum += __shfl_xor_sync(0xffffffffu, sum, o);
        sq  += __shfl_xor_sync(0xffffffffu, sq,  o);
    }
    float mean = sum * (1.0f / CDIM);
    float var  = sq * (1.0f / CDIM) - mean * mean;
    float rstd = rsqrtf(var + 1e-5f);

    float4 xa = ((const float4*)x)[lane];
    float4 xc = ((const float4*)x)[lane + 32];
    float4 w0 = ((const float4*)w)[lane];
    float4 w1 = ((const float4*)w)[lane + 32];
    float4 b0 = ((const float4*)b)[lane];
    float4 b1 = ((const float4*)b)[lane + 32];
    float4 g0 = ((const float4*)gamma)[lane];
    float4 g1 = ((const float4*)gamma)[lane + 32];

    float4 o0, o1;
    o0.x = xa.x + g0.x * ((a.x - mean) * rstd * w0.x + b0.x);
    o0.y = xa.y + g0.y * ((a.y - mean) * rstd * w0.y + b0.y);
    o0.z = xa.z + g0.z * ((a.z - mean) * rstd * w0.z + b0.z);
    o0.w = xa.w + g0.w * ((a.w - mean) * rstd * w0.w + b0.w);
    o1.x = xc.x + g1.x * ((c.x - mean) * rstd * w1.x + b1.x);
    o1.y = xc.y + g1.y * ((c.y - mean) * rstd * w1.y + b1.y);
    o1.z = xc.z + g1.z * ((c.z - mean) * rstd * w1.z + b1.z);
    o1.w = xc.w + g1.w * ((c.w - mean) * rstd * w1.w + b1.w);

    float4* op = (float4*)(out + (size_t)gwarp * CDIM);
    op[lane] = o0;
    op[lane + 32] = o1;
}

// ---------------- launch ----------------
extern "C" void kernel_launch(void* const* d_in, const int* in_sizes, int n_in,
                              void* d_out, int out_size)
{
    const float* x0      = (const float*)d_in[0];
    const float* x1      = (const float*)d_in[1];
    const float* qk_w    = (const float*)d_in[2];
    const float* v_w     = (const float*)d_in[3];
    const float* merge_w = (const float*)d_in[4];
    const float* ln1_w   = (const float*)d_in[5];
    const float* ln1_b   = (const float*)d_in[6];
    const float* ln2_w   = (const float*)d_in[7];
    const float* ln2_b   = (const float*)d_in[8];
    const float* fc1_w   = (const float*)d_in[9];
    const float* fc1_b   = (const float*)d_in[10];
    const float* fc2_w   = (const float*)d_in[11];
    const float* fc2_b   = (const float*)d_in[12];
    const float* gamma   = (const float*)d_in[13];
    float* out = (float*)d_out;

    float *n_, *qk_, *v_, *m_, *xm_, *h1_, *h2_, *pacc_, *pm_, *pl_;
    cudaGetSymbolAddress((void**)&n_,   g_n);
    cudaGetSymbolAddress((void**)&qk_,  g_qk);
    cudaGetSymbolAddress((void**)&v_,   g_v);
    cudaGetSymbolAddress((void**)&m_,   g_m);
    cudaGetSymbolAddress((void**)&xm_,  g_xm);
    cudaGetSymbolAddress((void**)&h1_,  g_h1);
    cudaGetSymbolAddress((void**)&h2_,  g_h2);
    cudaGetSymbolAddress((void**)&pacc_, g_pacc);
    cudaGetSymbolAddress((void**)&pm_,   g_pm);
    cudaGetSymbolAddress((void**)&pl_,   g_pl);

    // 1. LayerNorm both streams
    ln1_kernel<<<TTOK / 8, 256>>>(x0, x1, ln1_w, ln1_b, n_);

    // 2. qk & v projections (fp32 SIMT f32x2, qk fused with scale 32^-0.25)
    dim3 gproj(CDIM / 64, TTOK / 64);
    gemm_kernel<<<gproj, 256>>>(n_, CDIM, qk_w, qk_, CDIM, CDIM, QK_SCALE);
    gemm_kernel<<<gproj, 256>>>(n_, CDIM, v_w,  v_,  CDIM, CDIM, 1.0f);

    // 3. split-K dual-direction flash attention + combine
    attn_kernel<<<dim3((SEQ / 256) * SPLIT, HEADS, 4), 128>>>(qk_, v_, pacc_, pm_, pl_);
    attn_combine_kernel<<<(NTASK * 32) / 256, 256>>>(pacc_, pm_, pl_, m_);

    // 4. build concat buffer: cols [0,256) = x, cols [256,512) = m @ merge_w^T (tf32)
    copyx_kernel<<<(TTOK * CDIM / 4 + 255) / 256, 256>>>(x0, x1, xm_);
    gemm_tf32<<<dim3(CDIM / 64, TTOK / 128), 256>>>(m_, CDIM, merge_w, nullptr, xm_ + CDIM, 2 * CDIM, CDIM, 0);

    // 5. fc1 + exact GELU (tf32)
    gemm_tf32<<<dim3(HID / 64, TTOK / 128), 256>>>(xm_, 2 * CDIM, fc1_w, fc1_b, h1_, HID, 2 * CDIM, 1);

    // 6. fc2 (tf32)
    gemm_tf32<<<dim3(CDIM / 64, TTOK / 128), 256>>>(h1_, HID, fc2_w, fc2_b, h2_, CDIM, HID, 0);

    // 7. residual + LN2 epilogue -> output
    final_kernel<<<TTOK / 8, 256>>>(x0, x1, h2_, gamma, ln2_w, ln2_b, out);
}

// round 9
// speedup vs baseline: 2.4473x; 1.3284x over previous
#include <cuda_runtime.h>
#include <math.h>
#include <stdint.h>

// Problem constants
#define BATCH 2
#define SEQ   2048
#define CDIM  256
#define HEADS 8
#define HDIM  32
#define TOK   4096          // tokens per stream (BATCH*SEQ)
#define TTOK  8192          // total tokens (both streams)
#define HID   1024

// qk scale: 32^-0.25 (applied to both sides in reference)
#define QK_SCALE 0.42044820762685725f

// ---------------- scratch (static device allocations) ----------------
__device__ float g_n [TTOK * CDIM];        // ln1 output
__device__ float g_qk[TTOK * CDIM];        // qk projection (scaled)
__device__ float g_v [TTOK * CDIM];        // v projection
__device__ float g_m [TTOK * CDIM];        // attention output
__device__ float g_xm[TTOK * 2 * CDIM];    // concat(x, m@merge_w^T), ld=512
__device__ float g_h1[TTOK * HID];         // fc1+gelu output
__device__ float g_h2[TTOK * CDIM];        // fc2 output

// ---------------- packed f32x2 helpers ----------------
typedef unsigned long long u64;
__device__ __forceinline__ u64 f2fma(u64 a, u64 b, u64 c) {
    u64 d; asm("fma.rn.f32x2 %0, %1, %2, %3;" : "=l"(d) : "l"(a), "l"(b), "l"(c)); return d;
}
__device__ __forceinline__ u64 f2mul(u64 a, u64 b) {
    u64 d; asm("mul.rn.f32x2 %0, %1, %2;" : "=l"(d) : "l"(a), "l"(b)); return d;
}
__device__ __forceinline__ u64 f2pack(float x) {
    u64 d; asm("mov.b64 %0, {%1, %1};" : "=l"(d) : "f"(x)); return d;
}
__device__ __forceinline__ float f2lo(u64 a) {
    float lo, hi; asm("mov.b64 {%0, %1}, %2;" : "=f"(lo), "=f"(hi) : "l"(a)); return lo;
}
__device__ __forceinline__ float f2hi(u64 a) {
    float lo, hi; asm("mov.b64 {%0, %1}, %2;" : "=f"(lo), "=f"(hi) : "l"(a)); return hi;
}

// ---------------- LayerNorm (warp per token) ----------------
__global__ void ln1_kernel(const float* __restrict__ x0, const float* __restrict__ x1,
                           const float* __restrict__ w, const float* __restrict__ b,
                           float* __restrict__ out)
{
    int gwarp = (blockIdx.x * blockDim.x + threadIdx.x) >> 5;
    int lane = threadIdx.x & 31;
    if (gwarp >= TTOK) return;
    const float* x = (gwarp < TOK) ? (x0 + (size_t)gwarp * CDIM)
                                   : (x1 + (size_t)(gwarp - TOK) * CDIM);
    float4 a = ((const float4*)x)[lane];
    float4 c = ((const float4*)x)[lane + 32];
    float sum = a.x + a.y + a.z + a.w + c.x + c.y + c.z + c.w;
    float sq  = a.x*a.x + a.y*a.y + a.z*a.z + a.w*a.w
              + c.x*c.x + c.y*c.y + c.z*c.z + c.w*c.w;
    #pragma unroll
    for (int o = 16; o; o >>= 1) {
        sum += __shfl_xor_sync(0xffffffffu, sum, o);
        sq  += __shfl_xor_sync(0xffffffffu, sq,  o);
    }
    float mean = sum * (1.0f / CDIM);
    float var  = sq * (1.0f / CDIM) - mean * mean;
    float rstd = rsqrtf(var + 1e-5f);

    float4 w0 = ((const float4*)w)[lane];
    float4 w1 = ((const float4*)w)[lane + 32];
    float4 b0 = ((const float4*)b)[lane];
    float4 b1 = ((const float4*)b)[lane + 32];
    float4 o0, o1;
    o0.x = (a.x - mean) * rstd * w0.x + b0.x;
    o0.y = (a.y - mean) * rstd * w0.y + b0.y;
    o0.z = (a.z - mean) * rstd * w0.z + b0.z;
    o0.w = (a.w - mean) * rstd * w0.w + b0.w;
    o1.x = (c.x - mean) * rstd * w1.x + b1.x;
    o1.y = (c.y - mean) * rstd * w1.y + b1.y;
    o1.z = (c.z - mean) * rstd * w1.z + b1.z;
    o1.w = (c.w - mean) * rstd * w1.w + b1.w;
    float4* op = (float4*)(out + (size_t)gwarp * CDIM);
    op[lane] = o0;
    op[lane + 32] = o1;
}

__device__ __forceinline__ float gelu_exact(float x) {
    return 0.5f * x * (1.0f + erff(x * 0.70710678118654752f));
}

// ---------------- fp32 SIMT GEMM w/ packed f32x2 (qk/v projections) ----------------
__global__ void gemm_kernel(const float* __restrict__ A, int lda,
                            const float* __restrict__ W,
                            float* __restrict__ Cc, int ldc,
                            int K, float scale)
{
    __shared__ float As[16][68];
    __shared__ float Bs[16][68];

    int tid = threadIdx.x;                 // 256 threads
    int m0 = blockIdx.y * 64;
    int n0 = blockIdx.x * 64;
    int lrow = tid >> 2;                   // 0..63
    int lk   = (tid & 3) << 2;             // 0,4,8,12
    const float* Aptr = A + (size_t)(m0 + lrow) * lda + lk;
    const float* Wptr = W + (size_t)(n0 + lrow) * K + lk;

    int ty = tid >> 4;
    int tx = tid & 15;

    u64 acc2[4][2];
    #pragma unroll
    for (int i = 0; i < 4; i++) { acc2[i][0] = 0ull; acc2[i][1] = 0ull; }

    for (int k0 = 0; k0 < K; k0 += 16) {
        float4 av = *(const float4*)(Aptr + k0);
        float4 wv = *(const float4*)(Wptr + k0);
        As[lk + 0][lrow] = av.x; As[lk + 1][lrow] = av.y;
        As[lk + 2][lrow] = av.z; As[lk + 3][lrow] = av.w;
        Bs[lk + 0][lrow] = wv.x; Bs[lk + 1][lrow] = wv.y;
        Bs[lk + 2][lrow] = wv.z; Bs[lk + 3][lrow] = wv.w;
        __syncthreads();
        #pragma unroll
        for (int kk = 0; kk < 16; kk++) {
            float4 a4 = *(const float4*)&As[kk][ty * 4];
            const u64* bp = (const u64*)&Bs[kk][tx * 4];
            u64 b0 = bp[0], b1 = bp[1];
            u64 a0 = f2pack(a4.x), a1 = f2pack(a4.y);
            u64 a2 = f2pack(a4.z), a3 = f2pack(a4.w);
            acc2[0][0] = f2fma(a0, b0, acc2[0][0]);
            acc2[0][1] = f2fma(a0, b1, acc2[0][1]);
            acc2[1][0] = f2fma(a1, b0, acc2[1][0]);
            acc2[1][1] = f2fma(a1, b1, acc2[1][1]);
            acc2[2][0] = f2fma(a2, b0, acc2[2][0]);
            acc2[2][1] = f2fma(a2, b1, acc2[2][1]);
            acc2[3][0] = f2fma(a3, b0, acc2[3][0]);
            acc2[3][1] = f2fma(a3, b1, acc2[3][1]);
        }
        __syncthreads();
    }

    u64 sp = f2pack(scale);
    #pragma unroll
    for (int i = 0; i < 4; i++) {
        int row = m0 + ty * 4 + i;
        u64 v0 = f2mul(acc2[i][0], sp);
        u64 v1 = f2mul(acc2[i][1], sp);
        float4 o;
        o.x = f2lo(v0); o.y = f2hi(v0);
        o.z = f2lo(v1); o.w = f2hi(v1);
        *(float4*)&Cc[(size_t)row * ldc + n0 + tx * 4] = o;
    }
}

// ---------------- tf32 helpers ----------------
__device__ __forceinline__ float to_tf32(float x) {
    uint32_t u; asm("cvt.rna.tf32.f32 %0, %1;" : "=r"(u) : "f"(x));
    return __uint_as_float(u);
}

__device__ __forceinline__ void mma_tf32(float* c, const float* a, const float* b) {
    asm volatile(
        "mma.sync.aligned.m16n8k8.row.col.f32.tf32.tf32.f32 "
        "{%0,%1,%2,%3}, {%4,%5,%6,%7}, {%8,%9}, {%0,%1,%2,%3};"
        : "+f"(c[0]), "+f"(c[1]), "+f"(c[2]), "+f"(c[3])
        : "r"(__float_as_uint(a[0])), "r"(__float_as_uint(a[1])),
          "r"(__float_as_uint(a[2])), "r"(__float_as_uint(a[3])),
          "r"(__float_as_uint(b[0])), "r"(__float_as_uint(b[1])));
}

// ---------------- tf32 tensor-core GEMM: C = act(A @ W^T + bias) ----------------
__global__ __launch_bounds__(256) void gemm_tf32(
    const float* __restrict__ A, int lda,
    const float* __restrict__ W,
    const float* __restrict__ bias,
    float* __restrict__ Cc, int ldc,
    int K, int act)
{
    __shared__ float As[128][36];
    __shared__ float Ws[64][36];

    int tid = threadIdx.x;
    int lane = tid & 31;
    int warp = tid >> 5;          // 0..7
    int warp_m = warp & 3;
    int warp_n = warp >> 2;
    int m0 = blockIdx.y * 128;
    int n0 = blockIdx.x * 64;

    int grp = lane >> 2;          // 0..7
    int tig = lane & 3;           // 0..3

    float acc[2][4][4];
    #pragma unroll
    for (int mt = 0; mt < 2; mt++)
        #pragma unroll
        for (int nt = 0; nt < 4; nt++)
            #pragma unroll
            for (int r = 0; r < 4; r++) acc[mt][nt][r] = 0.0f;

    for (int k0 = 0; k0 < K; k0 += 32) {
        #pragma unroll
        for (int i = 0; i < 4; i++) {
            int idx = tid + i * 256;
            int row = idx >> 3;
            int kc  = (idx & 7) << 2;
            float4 v = *(const float4*)&A[(size_t)(m0 + row) * lda + k0 + kc];
            As[row][kc + 0] = to_tf32(v.x);
            As[row][kc + 1] = to_tf32(v.y);
            As[row][kc + 2] = to_tf32(v.z);
            As[row][kc + 3] = to_tf32(v.w);
        }
        #pragma unroll
        for (int i = 0; i < 2; i++) {
            int idx = tid + i * 256;
            int row = idx >> 3;
            int kc  = (idx & 7) << 2;
            float4 v = *(const float4*)&W[(size_t)(n0 + row) * K + k0 + kc];
            Ws[row][kc + 0] = to_tf32(v.x);
            Ws[row][kc + 1] = to_tf32(v.y);
            Ws[row][kc + 2] = to_tf32(v.z);
            Ws[row][kc + 3] = to_tf32(v.w);
        }
        __syncthreads();

        #pragma unroll
        for (int ks = 0; ks < 4; ks++) {
            int kb = ks * 8;
            float a[2][4];
            #pragma unroll
            for (int mt = 0; mt < 2; mt++) {
                int rb = warp_m * 32 + mt * 16;
                a[mt][0] = As[rb + grp    ][kb + tig];
                a[mt][1] = As[rb + grp + 8][kb + tig];
                a[mt][2] = As[rb + grp    ][kb + tig + 4];
                a[mt][3] = As[rb + grp + 8][kb + tig + 4];
            }
            float b[4][2];
            #pragma unroll
            for (int nt = 0; nt < 4; nt++) {
                int nb = warp_n * 32 + nt * 8 + grp;
                b[nt][0] = Ws[nb][kb + tig];
                b[nt][1] = Ws[nb][kb + tig + 4];
            }
            #pragma unroll
            for (int mt = 0; mt < 2; mt++)
                #pragma unroll
                for (int nt = 0; nt < 4; nt++)
                    mma_tf32(acc[mt][nt], a[mt], b[nt]);
        }
        __syncthreads();
    }

    #pragma unroll
    for (int mt = 0; mt < 2; mt++) {
        #pragma unroll
        for (int nt = 0; nt < 4; nt++) {
            int r = m0 + warp_m * 32 + mt * 16 + grp;
            int c = n0 + warp_n * 32 + nt * 8 + tig * 2;
            float b0 = bias ? bias[c]     : 0.0f;
            float b1 = bias ? bias[c + 1] : 0.0f;
            float v0 = acc[mt][nt][0] + b0;
            float v1 = acc[mt][nt][1] + b1;
            float v2 = acc[mt][nt][2] + b0;
            float v3 = acc[mt][nt][3] + b1;
            if (act) { v0 = gelu_exact(v0); v1 = gelu_exact(v1);
                       v2 = gelu_exact(v2); v3 = gelu_exact(v3); }
            float2 p0 = make_float2(v0, v1);
            float2 p1 = make_float2(v2, v3);
            *(float2*)&Cc[(size_t)r * ldc + c]       = p0;
            *(float2*)&Cc[(size_t)(r + 8) * ldc + c] = p1;
        }
    }
}

// ---------------- tensor-core dual-direction flash attention ----------------
// Block: 64 q-rows (4 warps x 16), loop over 2048 keys in 64-key tiles.
// dir=0: Q=qk(s0), K=qk(s1), V=v(s1) -> m(s0);  dir=1: swapped.
#define ATT_M 64
#define ATT_N 64
__global__ __launch_bounds__(128)
void attn_tc_kernel(const float* __restrict__ qk, const float* __restrict__ v,
                    float* __restrict__ out)
{
    __shared__ float Kt[32][72];        // [dim][key]   (B-frag reads conflict-free)
    __shared__ float Vs[64][40];        // [key][dim]   (B-frag reads conflict-free)
    __shared__ float Ps[4][16][68];     // per-warp P tile (A-frag reads conflict-free)

    const int combo = blockIdx.z;
    const int dir = combo >> 1, bb = combo & 1;
    const int h = blockIdx.y;
    const int q_base = dir * TOK + bb * SEQ;
    const int k_base = (dir ^ 1) * TOK + bb * SEQ;
    const int tid = threadIdx.x;
    const int warp = tid >> 5, lane = tid & 31;
    const int grp = lane >> 2, tig = lane & 3;
    const int m0 = blockIdx.x * ATT_M + warp * 16;

    // Q fragments (A-layout), rows m0+grp / m0+grp+8, k = 8s+tig / 8s+tig+4
    float qa[4][4];
    {
        const float* qr0 = &qk[(size_t)(q_base + m0 + grp) * CDIM + h * HDIM];
        const float* qr1 = &qk[(size_t)(q_base + m0 + grp + 8) * CDIM + h * HDIM];
        #pragma unroll
        for (int s = 0; s < 4; s++) {
            qa[s][0] = to_tf32(qr0[8 * s + tig]);
            qa[s][1] = to_tf32(qr1[8 * s + tig]);
            qa[s][2] = to_tf32(qr0[8 * s + tig + 4]);
            qa[s][3] = to_tf32(qr1[8 * s + tig + 4]);
        }
    }

    float o[4][4];
    #pragma unroll
    for (int nt = 0; nt < 4; nt++)
        #pragma unroll
        for (int r = 0; r < 4; r++) o[nt][r] = 0.0f;
    float m_lo = -1e30f, m_hi = -1e30f, l_lo = 0.0f, l_hi = 0.0f;

    for (int kt = 0; kt < SEQ; kt += ATT_N) {
        // load K (transposed) and V tiles, rounding to tf32
        #pragma unroll
        for (int i = 0; i < 4; i++) {
            int idx = tid + i * 128;          // 0..511
            int key = idx >> 3;
            int c4  = (idx & 7) << 2;
            size_t goff = (size_t)(k_base + kt + key) * CDIM + h * HDIM + c4;
            float4 kv = *(const float4*)&qk[goff];
            Kt[c4 + 0][key] = to_tf32(kv.x);
            Kt[c4 + 1][key] = to_tf32(kv.y);
            Kt[c4 + 2][key] = to_tf32(kv.z);
            Kt[c4 + 3][key] = to_tf32(kv.w);
            float4 vv = *(const float4*)&v[goff];
            Vs[key][c4 + 0] = to_tf32(vv.x);
            Vs[key][c4 + 1] = to_tf32(vv.y);
            Vs[key][c4 + 2] = to_tf32(vv.z);
            Vs[key][c4 + 3] = to_tf32(vv.w);
        }
        __syncthreads();

        // ---- S = Q @ K^T : s[8 ntiles][4] ----
        float s[8][4];
        #pragma unroll
        for (int nt = 0; nt < 8; nt++)
            #pragma unroll
            for (int r = 0; r < 4; r++) s[nt][r] = 0.0f;
        #pragma unroll
        for (int ks = 0; ks < 4; ks++) {
            #pragma unroll
            for (int nt = 0; nt < 8; nt++) {
                float bfr[2];
                bfr[0] = Kt[8 * ks + tig][nt * 8 + grp];
                bfr[1] = Kt[8 * ks + tig + 4][nt * 8 + grp];
                mma_tf32(s[nt], qa[ks], bfr);
            }
        }

        // ---- online softmax (rows grp / grp+8, quad shfl reductions) ----
        float mx_lo = -1e30f, mx_hi = -1e30f;
        #pragma unroll
        for (int nt = 0; nt < 8; nt++) {
            mx_lo = fmaxf(mx_lo, fmaxf(s[nt][0], s[nt][1]));
            mx_hi = fmaxf(mx_hi, fmaxf(s[nt][2], s[nt][3]));
        }
        mx_lo = fmaxf(mx_lo, __shfl_xor_sync(0xffffffffu, mx_lo, 1));
        mx_lo = fmaxf(mx_lo, __shfl_xor_sync(0xffffffffu, mx_lo, 2));
        mx_hi = fmaxf(mx_hi, __shfl_xor_sync(0xffffffffu, mx_hi, 1));
        mx_hi = fmaxf(mx_hi, __shfl_xor_sync(0xffffffffu, mx_hi, 2));

        float mn_lo = fmaxf(m_lo, mx_lo);
        float mn_hi = fmaxf(m_hi, mx_hi);
        float corr_lo = __expf(m_lo - mn_lo);
        float corr_hi = __expf(m_hi - mn_hi);
        m_lo = mn_lo; m_hi = mn_hi;
        l_lo *= corr_lo; l_hi *= corr_hi;
        #pragma unroll
        for (int nt = 0; nt < 4; nt++) {
            o[nt][0] *= corr_lo; o[nt][1] *= corr_lo;
            o[nt][2] *= corr_hi; o[nt][3] *= corr_hi;
        }

        float sum_lo = 0.0f, sum_hi = 0.0f;
        #pragma unroll
        for (int nt = 0; nt < 8; nt++) {
            s[nt][0] = __expf(s[nt][0] - m_lo);
            s[nt][1] = __expf(s[nt][1] - m_lo);
            s[nt][2] = __expf(s[nt][2] - m_hi);
            s[nt][3] = __expf(s[nt][3] - m_hi);
            sum_lo += s[nt][0] + s[nt][1];
            sum_hi += s[nt][2] + s[nt][3];
        }
        sum_lo += __shfl_xor_sync(0xffffffffu, sum_lo, 1);
        sum_lo += __shfl_xor_sync(0xffffffffu, sum_lo, 2);
        sum_hi += __shfl_xor_sync(0xffffffffu, sum_hi, 1);
        sum_hi += __shfl_xor_sync(0xffffffffu, sum_hi, 2);
        l_lo += sum_lo; l_hi += sum_hi;

        // ---- stage P to SMEM (tf32) ----
        #pragma unroll
        for (int nt = 0; nt < 8; nt++) {
            float2 plo = make_float2(to_tf32(s[nt][0]), to_tf32(s[nt][1]));
            float2 phi = make_float2(to_tf32(s[nt][2]), to_tf32(s[nt][3]));
            *(float2*)&Ps[warp][grp][nt * 8 + 2 * tig]     = plo;
            *(float2*)&Ps[warp][grp + 8][nt * 8 + 2 * tig] = phi;
        }
        __syncwarp();

        // ---- O += P @ V ----
        #pragma unroll
        for (int ks = 0; ks < 8; ks++) {
            float a[4];
            a[0] = Ps[warp][grp][8 * ks + tig];
            a[1] = Ps[warp][grp + 8][8 * ks + tig];
            a[2] = Ps[warp][grp][8 * ks + tig + 4];
            a[3] = Ps[warp][grp + 8][8 * ks + tig + 4];
            #pragma unroll
            for (int nt = 0; nt < 4; nt++) {
                float bfr[2];
                bfr[0] = Vs[8 * ks + tig][nt * 8 + grp];
                bfr[1] = Vs[8 * ks + tig + 4][nt * 8 + grp];
                mma_tf32(o[nt], a, bfr);
            }
        }
        __syncthreads();
    }

    // ---- normalize & write ----
    float inv_lo = 1.0f / l_lo;
    float inv_hi = 1.0f / l_hi;
    float* or0 = &out[(size_t)(q_base + m0 + grp) * CDIM + h * HDIM];
    float* or1 = &out[(size_t)(q_base + m0 + grp + 8) * CDIM + h * HDIM];
    #pragma unroll
    for (int nt = 0; nt < 4; nt++) {
        *(float2*)&or0[nt * 8 + 2 * tig] = make_float2(o[nt][0] * inv_lo, o[nt][1] * inv_lo);
        *(float2*)&or1[nt * 8 + 2 * tig] = make_float2(o[nt][2] * inv_hi, o[nt][3] * inv_hi);
    }
}

// ---------------- copy x into concat buffer (cols 0..255 of g_xm, ld=512) ----------------
__global__ void copyx_kernel(const float* __restrict__ x0, const float* __restrict__ x1,
                             float* __restrict__ xm)
{
    int idx = blockIdx.x * blockDim.x + threadIdx.x;
    if (idx >= TTOK * CDIM / 4) return;
    int tok = idx >> 6;
    int c4  = idx & 63;
    const float4* src = (const float4*)((tok < TOK) ? (x0 + (size_t)tok * CDIM)
                                                    : (x1 + (size_t)(tok - TOK) * CDIM));
    ((float4*)(xm + (size_t)tok * (2 * CDIM)))[c4] = src[c4];
}

// ---------------- final: out = x + gamma * LN(h2; ln2_w, ln2_b) ----------------
__global__ void final_kernel(const float* __restrict__ x0, const float* __restrict__ x1,
                             const float* __restrict__ h2, const float* __restrict__ gamma,
                             const float* __restrict__ w, const float* __restrict__ b,
                             float* __restrict__ out)
{
    int gwarp = (blockIdx.x * blockDim.x + threadIdx.x) >> 5;
    int lane = threadIdx.x & 31;
    if (gwarp >= TTOK) return;
    const float* x = (gwarp < TOK) ? (x0 + (size_t)gwarp * CDIM)
                                   : (x1 + (size_t)(gwarp - TOK) * CDIM);
    const float* hh = h2 + (size_t)gwarp * CDIM;

    float4 a = ((const float4*)hh)[lane];
    float4 c = ((const float4*)hh)[lane + 32];
    float sum = a.x + a.y + a.z + a.w + c.x + c.y + c.z + c.w;
    float sq  = a.x*a.x + a.y*a.y + a.z*a.z + a.w*a.w
              + c.x*c.x + c.y*c.y + c.z*c.z + c.w*c.w;
    #pragma unroll
    for (int o = 16; o; o >>= 1) {
        sum += __shfl_xor_sync(0xffffffffu, sum, o);
        sq  += __shfl_xor_sync(0xffffffffu, sq,  o);
    }
    float mean = sum * (1.0f / CDIM);
    float var  = sq * (1.0f / CDIM) - mean * mean;
    float rstd = rsqrtf(var + 1e-5f);

    float4 xa = ((const float4*)x)[lane];
    float4 xc = ((const float4*)x)[lane + 32];
    float4 w0 = ((const float4*)w)[lane];
    float4 w1 = ((const float4*)w)[lane + 32];
    float4 b0 = ((const float4*)b)[lane];
    float4 b1 = ((const float4*)b)[lane + 32];
    float4 g0 = ((const float4*)gamma)[lane];
    float4 g1 = ((const float4*)gamma)[lane + 32];

    float4 o0, o1;
    o0.x = xa.x + g0.x * ((a.x - mean) * rstd * w0.x + b0.x);
    o0.y = xa.y + g0.y * ((a.y - mean) * rstd * w0.y + b0.y);
    o0.z = xa.z + g0.z * ((a.z - mean) * rstd * w0.z + b0.z);
    o0.w = xa.w + g0.w * ((a.w - mean) * rstd * w0.w + b0.w);
    o1.x = xc.x + g1.x * ((c.x - mean) * rstd * w1.x + b1.x);
    o1.y = xc.y + g1.y * ((c.y - mean) * rstd * w1.y + b1.y);
    o1.z = xc.z + g1.z * ((c.z - mean) * rstd * w1.z + b1.z);
    o1.w = xc.w + g1.w * ((c.w - mean) * rstd * w1.w + b1.w);

    float4* op = (float4*)(out + (size_t)gwarp * CDIM);
    op[lane] = o0;
    op[lane + 32] = o1;
}

// ---------------- launch ----------------
extern "C" void kernel_launch(void* const* d_in, const int* in_sizes, int n_in,
                              void* d_out, int out_size)
{
    const float* x0      = (const float*)d_in[0];
    const float* x1      = (const float*)d_in[1];
    const float* qk_w    = (const float*)d_in[2];
    const float* v_w     = (const float*)d_in[3];
    const float* merge_w = (const float*)d_in[4];
    const float* ln1_w   = (const float*)d_in[5];
    const float* ln1_b   = (const float*)d_in[6];
    const float* ln2_w   = (const float*)d_in[7];
    const float* ln2_b   = (const float*)d_in[8];
    const float* fc1_w   = (const float*)d_in[9];
    const float* fc1_b   = (const float*)d_in[10];
    const float* fc2_w   = (const float*)d_in[11];
    const float* fc2_b   = (const float*)d_in[12];
    const float* gamma   = (const float*)d_in[13];
    float* out = (float*)d_out;

    float *n_, *qk_, *v_, *m_, *xm_, *h1_, *h2_;
    cudaGetSymbolAddress((void**)&n_,   g_n);
    cudaGetSymbolAddress((void**)&qk_,  g_qk);
    cudaGetSymbolAddress((void**)&v_,   g_v);
    cudaGetSymbolAddress((void**)&m_,   g_m);
    cudaGetSymbolAddress((void**)&xm_,  g_xm);
    cudaGetSymbolAddress((void**)&h1_,  g_h1);
    cudaGetSymbolAddress((void**)&h2_,  g_h2);

    // 1. LayerNorm both streams
    ln1_kernel<<<TTOK / 8, 256>>>(x0, x1, ln1_w, ln1_b, n_);

    // 2. qk & v projections (fp32 SIMT f32x2, qk fused with scale 32^-0.25)
    dim3 gproj(CDIM / 64, TTOK / 64);
    gemm_kernel<<<gproj, 256>>>(n_, CDIM, qk_w, qk_, CDIM, CDIM, QK_SCALE);
    gemm_kernel<<<gproj, 256>>>(n_, CDIM, v_w,  v_,  CDIM, CDIM, 1.0f);

    // 3. tensor-core dual-direction flash attention
    attn_tc_kernel<<<dim3(SEQ / ATT_M, HEADS, 4), 128>>>(qk_, v_, m_);

    // 4. build concat buffer: cols [0,256) = x, cols [256,512) = m @ merge_w^T (tf32)
    copyx_kernel<<<(TTOK * CDIM / 4 + 255) / 256, 256>>>(x0, x1, xm_);
    gemm_tf32<<<dim3(CDIM / 64, TTOK / 128), 256>>>(m_, CDIM, merge_w, nullptr, xm_ + CDIM, 2 * CDIM, CDIM, 0);

    // 5. fc1 + exact GELU (tf32)
    gemm_tf32<<<dim3(HID / 64, TTOK / 128), 256>>>(xm_, 2 * CDIM, fc1_w, fc1_b, h1_, HID, 2 * CDIM, 1);

    // 6. fc2 (tf32)
    gemm_tf32<<<dim3(CDIM / 64, TTOK / 128), 256>>>(h1_, HID, fc2_w, fc2_b, h2_, CDIM, HID, 0);

    // 7. residual + LN2 epilogue -> output
    final_kernel<<<TTOK / 8, 256>>>(x0, x1, h2_, gamma, ln2_w, ln2_b, out);
}